// round 1
// baseline (speedup 1.0000x reference)
#include <cuda_runtime.h>
#include <cuda_bf16.h>
#include <math.h>

#define TT 2048
#define HIDDEN 2048
#define NH 16
#define DN 128
#define DR 64
#define DVV 128
#define KV_LORA 512
#define DQ (DN + DR)          // 192
#define QW (NH * DQ)          // 3072
#define KVW (NH * (DN + DVV)) // 4096
#define LATW (KV_LORA + DR)   // 576

// ---------------- scratch (device globals; no allocations allowed) ----------
__device__ float g_q[TT * QW];        // q projection, q_pe roped in-place
__device__ float g_latent[TT * LATW]; // hidden @ w_kv_a
__device__ float g_kva[TT * KV_LORA]; // rmsnormed latent
__device__ float g_kpe[TT * DR];      // roped k_pe
__device__ float g_kv[TT * KVW];      // kv_a @ w_kv_b
__device__ float g_attn[TT * NH * DVV];

// ---------------- generic SGEMM: C[M,N] = A[M,K] @ B[K,N], row-major --------
// 64x64 tile, BK=16, 256 threads, 4x4 per thread.
__global__ __launch_bounds__(256) void sgemm64(
    const float* __restrict__ A, const float* __restrict__ B,
    float* __restrict__ C, int M, int N, int K)
{
    __shared__ float As[16][68];
    __shared__ float Bs[16][68];
    const int tid = threadIdx.x;
    const int tx = tid & 15, ty = tid >> 4;
    const int row0 = blockIdx.y * 64;
    const int col0 = blockIdx.x * 64;

    float acc[4][4] = {};

    for (int k0 = 0; k0 < K; k0 += 16) {
        // A tile 64x16 -> As[k][m] (transposed)
        {
            int r = tid >> 2;
            int c = (tid & 3) * 4;
            float4 v = *reinterpret_cast<const float4*>(&A[(size_t)(row0 + r) * K + k0 + c]);
            As[c + 0][r] = v.x; As[c + 1][r] = v.y; As[c + 2][r] = v.z; As[c + 3][r] = v.w;
        }
        // B tile 16x64 -> Bs[k][n]
        {
            int kk = tid >> 4;
            int c = (tid & 15) * 4;
            float4 v = *reinterpret_cast<const float4*>(&B[(size_t)(k0 + kk) * N + col0 + c]);
            Bs[kk][c + 0] = v.x; Bs[kk][c + 1] = v.y; Bs[kk][c + 2] = v.z; Bs[kk][c + 3] = v.w;
        }
        __syncthreads();

        #pragma unroll
        for (int kk = 0; kk < 16; kk++) {
            float4 a = *reinterpret_cast<const float4*>(&As[kk][ty * 4]);
            float4 b = *reinterpret_cast<const float4*>(&Bs[kk][tx * 4]);
            float av[4] = {a.x, a.y, a.z, a.w};
            float bv[4] = {b.x, b.y, b.z, b.w};
            #pragma unroll
            for (int i = 0; i < 4; i++)
                #pragma unroll
                for (int j = 0; j < 4; j++)
                    acc[i][j] += av[i] * bv[j];
        }
        __syncthreads();
    }

    #pragma unroll
    for (int i = 0; i < 4; i++) {
        float4 v = make_float4(acc[i][0], acc[i][1], acc[i][2], acc[i][3]);
        *reinterpret_cast<float4*>(&C[(size_t)(row0 + ty * 4 + i) * N + col0 + tx * 4]) = v;
    }
}

// ---------------- rmsnorm over latent[:, :512] -------------------------------
__global__ __launch_bounds__(256) void rmsnorm_kernel(
    const float* __restrict__ latent, const float* __restrict__ w,
    float* __restrict__ out)
{
    const int t = blockIdx.x;
    const float* x = latent + (size_t)t * LATW;
    __shared__ float red[8];
    float ss = 0.f;
    for (int i = threadIdx.x; i < KV_LORA; i += 256) { float v = x[i]; ss += v * v; }
    #pragma unroll
    for (int o = 16; o > 0; o >>= 1) ss += __shfl_xor_sync(~0u, ss, o);
    if ((threadIdx.x & 31) == 0) red[threadIdx.x >> 5] = ss;
    __syncthreads();
    if (threadIdx.x == 0) {
        float v = 0.f;
        #pragma unroll
        for (int i = 0; i < 8; i++) v += red[i];
        red[0] = v;
    }
    __syncthreads();
    const float inv = rsqrtf(red[0] / (float)KV_LORA + 1e-6f);
    for (int i = threadIdx.x; i < KV_LORA; i += 256)
        out[(size_t)t * KV_LORA + i] = x[i] * inv * w[i];
}

// ---------------- non-neox RoPE ----------------------------------------------
__device__ __forceinline__ void rope_pair(float p, int i, float& x1, float& x2) {
    float inv = 1.0f / powf(10000.0f, (float)(2 * i) / (float)DR);
    float f = p * inv;
    float c = cosf(f), s = sinf(f);
    float o1 = x1 * c - x2 * s;
    float o2 = x2 * c + x1 * s;
    x1 = o1; x2 = o2;
}

__global__ __launch_bounds__(256) void rope_k_kernel(
    const float* __restrict__ latent, float* __restrict__ kpe)
{
    int idx = blockIdx.x * blockDim.x + threadIdx.x;
    if (idx >= TT * (DR / 2)) return;
    int t = idx / (DR / 2), i = idx % (DR / 2);
    float x1 = latent[(size_t)t * LATW + KV_LORA + 2 * i];
    float x2 = latent[(size_t)t * LATW + KV_LORA + 2 * i + 1];
    rope_pair((float)t, i, x1, x2);
    kpe[(size_t)t * DR + 2 * i]     = x1;
    kpe[(size_t)t * DR + 2 * i + 1] = x2;
}

__global__ __launch_bounds__(256) void rope_q_kernel(float* __restrict__ q)
{
    int idx = blockIdx.x * blockDim.x + threadIdx.x;
    if (idx >= TT * NH * (DR / 2)) return;
    int i = idx & 31;
    int h = (idx >> 5) & (NH - 1);
    int t = idx >> 9;
    float* base = q + (size_t)t * QW + h * DQ + DN;
    float x1 = base[2 * i], x2 = base[2 * i + 1];
    rope_pair((float)t, i, x1, x2);
    base[2 * i] = x1; base[2 * i + 1] = x2;
}

// ---------------- flash-style causal attention -------------------------------
// grid (T/64, H), 256 threads (16x16), 4 q-rows x (4 score-cols / 8 v-dims) per thread.
#define BM 64
#define BN 64
#define ATTN_SMEM ((DQ * BM + DQ * BN + BN * DVV + BN * BM) * 4) // 147456 B

__global__ __launch_bounds__(256) void mla_attn_kernel(
    const float* __restrict__ q, const float* __restrict__ kv,
    const float* __restrict__ kpe, float* __restrict__ out)
{
    extern __shared__ float smem[];
    float* sQt = smem;               // [DQ][BM]
    float* sKt = sQt + DQ * BM;      // [DQ][BN]
    float* sV  = sKt + DQ * BN;      // [BN][DVV]
    float* sPt = sV + BN * DVV;      // [BN][BM]

    const int h = blockIdx.y;
    const int q0 = blockIdx.x * BM;
    const int tid = threadIdx.x;
    const int tx = tid & 15, ty = tid >> 4;
    const float scale = rsqrtf((float)DQ);

    // Load Q tile transposed, pre-scaled
    for (int idx = tid; idx < BM * DQ; idx += 256) {
        int r = idx / DQ, d = idx % DQ;
        sQt[d * BM + r] = q[(size_t)(q0 + r) * QW + h * DQ + d] * scale;
    }

    float acc[4][8] = {};
    float m[4], l[4];
    #pragma unroll
    for (int i = 0; i < 4; i++) { m[i] = -1e30f; l[i] = 0.f; }

    const int jt_end = blockIdx.x; // BM == BN

    for (int jt = 0; jt <= jt_end; jt++) {
        const int k0 = jt * BN;
        __syncthreads(); // protect sKt/sV (and sQt on iter 0) before overwrite
        for (int idx = tid; idx < BN * DQ; idx += 256) {
            int r = idx / DQ, d = idx % DQ;
            float v = (d < DN) ? kv[(size_t)(k0 + r) * KVW + h * (DN + DVV) + d]
                               : kpe[(size_t)(k0 + r) * DR + (d - DN)];
            sKt[d * BN + r] = v;
        }
        for (int idx = tid; idx < BN * DVV; idx += 256) {
            int r = idx / DVV, d = idx % DVV;
            sV[r * DVV + d] = kv[(size_t)(k0 + r) * KVW + h * (DN + DVV) + DN + d];
        }
        __syncthreads();

        // scores: s = Qt^T @ Kt over 192 dims
        float s[4][4] = {};
        #pragma unroll 4
        for (int kk = 0; kk < DQ; kk++) {
            float4 a = *reinterpret_cast<const float4*>(&sQt[kk * BM + ty * 4]);
            float4 b = *reinterpret_cast<const float4*>(&sKt[kk * BN + tx * 4]);
            float av[4] = {a.x, a.y, a.z, a.w};
            float bv[4] = {b.x, b.y, b.z, b.w};
            #pragma unroll
            for (int i = 0; i < 4; i++)
                #pragma unroll
                for (int j = 0; j < 4; j++)
                    s[i][j] += av[i] * bv[j];
        }

        if (jt == jt_end) { // diagonal tile: causal mask
            #pragma unroll
            for (int i = 0; i < 4; i++) {
                int qr = ty * 4 + i;
                #pragma unroll
                for (int j = 0; j < 4; j++)
                    if (tx * 4 + j > qr) s[i][j] = -1e30f;
            }
        }

        // online softmax (row groups span 16 lanes within a warp)
        #pragma unroll
        for (int i = 0; i < 4; i++) {
            float mx = fmaxf(fmaxf(s[i][0], s[i][1]), fmaxf(s[i][2], s[i][3]));
            #pragma unroll
            for (int o = 1; o < 16; o <<= 1) mx = fmaxf(mx, __shfl_xor_sync(~0u, mx, o));
            float mnew = fmaxf(m[i], mx);
            float alpha = __expf(m[i] - mnew);
            float rs = 0.f;
            #pragma unroll
            for (int j = 0; j < 4; j++) { s[i][j] = __expf(s[i][j] - mnew); rs += s[i][j]; }
            #pragma unroll
            for (int o = 1; o < 16; o <<= 1) rs += __shfl_xor_sync(~0u, rs, o);
            l[i] = l[i] * alpha + rs;
            m[i] = mnew;
            #pragma unroll
            for (int d = 0; d < 8; d++) acc[i][d] *= alpha;
        }

        // stash P transposed
        #pragma unroll
        for (int i = 0; i < 4; i++)
            #pragma unroll
            for (int j = 0; j < 4; j++)
                sPt[(tx * 4 + j) * BM + ty * 4 + i] = s[i][j];
        __syncthreads();

        // O += P @ V
        #pragma unroll 2
        for (int j = 0; j < BN; j++) {
            float4 p4 = *reinterpret_cast<const float4*>(&sPt[j * BM + ty * 4]);
            float pv[4] = {p4.x, p4.y, p4.z, p4.w};
            float4 v0 = *reinterpret_cast<const float4*>(&sV[j * DVV + tx * 8]);
            float4 v1 = *reinterpret_cast<const float4*>(&sV[j * DVV + tx * 8 + 4]);
            float vv[8] = {v0.x, v0.y, v0.z, v0.w, v1.x, v1.y, v1.z, v1.w};
            #pragma unroll
            for (int i = 0; i < 4; i++)
                #pragma unroll
                for (int d = 0; d < 8; d++)
                    acc[i][d] += pv[i] * vv[d];
        }
    }

    #pragma unroll
    for (int i = 0; i < 4; i++) {
        float inv = 1.0f / l[i];
        size_t base = (size_t)(q0 + ty * 4 + i) * (NH * DVV) + h * DVV + tx * 8;
        float4 o0 = make_float4(acc[i][0] * inv, acc[i][1] * inv, acc[i][2] * inv, acc[i][3] * inv);
        float4 o1 = make_float4(acc[i][4] * inv, acc[i][5] * inv, acc[i][6] * inv, acc[i][7] * inv);
        *reinterpret_cast<float4*>(&out[base]) = o0;
        *reinterpret_cast<float4*>(&out[base + 4]) = o1;
    }
}

// ---------------- launch ------------------------------------------------------
extern "C" void kernel_launch(void* const* d_in, const int* in_sizes, int n_in,
                              void* d_out, int out_size)
{
    // inputs: 0 positions (unused; == arange), 1 hidden, 2 w_q, 3 w_kv_a,
    //         4 kv_a_ln_w, 5 w_kv_b, 6 w_o
    const float* hidden = (const float*)d_in[1];
    const float* w_q    = (const float*)d_in[2];
    const float* w_kv_a = (const float*)d_in[3];
    const float* ln_w   = (const float*)d_in[4];
    const float* w_kv_b = (const float*)d_in[5];
    const float* w_o    = (const float*)d_in[6];
    float* out = (float*)d_out;

    float *q_p, *lat_p, *kva_p, *kpe_p, *kv_p, *attn_p;
    cudaGetSymbolAddress((void**)&q_p,    g_q);
    cudaGetSymbolAddress((void**)&lat_p,  g_latent);
    cudaGetSymbolAddress((void**)&kva_p,  g_kva);
    cudaGetSymbolAddress((void**)&kpe_p,  g_kpe);
    cudaGetSymbolAddress((void**)&kv_p,   g_kv);
    cudaGetSymbolAddress((void**)&attn_p, g_attn);

    cudaFuncSetAttribute(mla_attn_kernel,
                         cudaFuncAttributeMaxDynamicSharedMemorySize, ATTN_SMEM);

    dim3 blk(256);
    // q = hidden @ w_q   [2048 x 3072]
    sgemm64<<<dim3(QW / 64, TT / 64), blk>>>(hidden, w_q, q_p, TT, QW, HIDDEN);
    // latent = hidden @ w_kv_a  [2048 x 576]
    sgemm64<<<dim3(LATW / 64, TT / 64), blk>>>(hidden, w_kv_a, lat_p, TT, LATW, HIDDEN);
    // kv_a = rmsnorm(latent[:, :512]) * w
    rmsnorm_kernel<<<TT, 256>>>(lat_p, ln_w, kva_p);
    // k_pe = rope(latent[:, 512:])
    rope_k_kernel<<<(TT * (DR / 2) + 255) / 256, 256>>>(lat_p, kpe_p);
    // kv = kv_a @ w_kv_b  [2048 x 4096]
    sgemm64<<<dim3(KVW / 64, TT / 64), blk>>>(kva_p, w_kv_b, kv_p, TT, KVW, KV_LORA);
    // rope q_pe in place
    rope_q_kernel<<<(TT * NH * (DR / 2) + 255) / 256, 256>>>(q_p);
    // attention
    mla_attn_kernel<<<dim3(TT / BM, NH), 256, ATTN_SMEM>>>(q_p, kv_p, kpe_p, attn_p);
    // out = attn @ w_o  [2048 x 2048]
    sgemm64<<<dim3(HIDDEN / 64, TT / 64), blk>>>(attn_p, w_o, out, TT, HIDDEN, NH * DVV);
}

// round 3
// speedup vs baseline: 1.3960x; 1.3960x over previous
#include <cuda_runtime.h>
#include <cuda_bf16.h>
#include <cstdint>
#include <math.h>

#define TT 2048
#define HIDDEN 2048
#define NH 16
#define DN 128
#define DR 64
#define DVV 128
#define KV_LORA 512
#define DQ (DN + DR)          // 192
#define QW (NH * DQ)          // 3072
#define KVW (NH * (DN + DVV)) // 4096
#define LATW (KV_LORA + DR)   // 576

// ---------------- scratch (device globals; no allocations allowed) ----------
__device__ float g_q[TT * QW];
__device__ float g_latent[TT * LATW];
__device__ float g_kva[TT * KV_LORA];
__device__ float g_kpe[TT * DR];
__device__ float g_kv[TT * KVW];
__device__ float g_attn[TT * NH * DVV];

// ---------------- tf32 helpers ------------------------------------------------
__device__ __forceinline__ uint32_t f2tf32(float x) {
    uint32_t r;
    asm("cvt.rna.tf32.f32 %0, %1;" : "=r"(r) : "f"(x));
    return r;
}

__device__ __forceinline__ void mma_tf32(float c[4], const uint32_t a[4], const uint32_t b[2]) {
    asm volatile(
        "mma.sync.aligned.m16n8k8.row.col.f32.tf32.tf32.f32 "
        "{%0,%1,%2,%3}, {%4,%5,%6,%7}, {%8,%9}, {%0,%1,%2,%3};"
        : "+f"(c[0]), "+f"(c[1]), "+f"(c[2]), "+f"(c[3])
        : "r"(a[0]), "r"(a[1]), "r"(a[2]), "r"(a[3]), "r"(b[0]), "r"(b[1]));
}

// ---------------- TF32 tensor-core GEMM: C[M,N] = A[M,K] @ B[K,N] ------------
// Block 128x128, BK=32, 256 threads (8 warps, warp tile 64x32).
// Requires: M % 128 == 0, K % 32 == 0, N % 4 == 0 (N tiles may be partial).
__global__ __launch_bounds__(256) void gemm_tf32(
    const float* __restrict__ A, const float* __restrict__ B,
    float* __restrict__ C, int M, int N, int K)
{
    __shared__ uint32_t As[128][36];  // [m][k], pad 4
    __shared__ uint32_t Bs[32][136];  // [k][n], pad 8

    const int tid  = threadIdx.x;
    const int lane = tid & 31, warp = tid >> 5;
    const int warpM = warp & 1;      // 0..1 -> 64-row slab
    const int warpN = warp >> 1;     // 0..3 -> 32-col slab
    const int gid = lane >> 2, tig = lane & 3;
    const int m0 = blockIdx.y * 128;
    const int n0 = blockIdx.x * 128;

    float c[4][4][4] = {};           // [mt][nt][frag]

    for (int k0 = 0; k0 < K; k0 += 32) {
        // A tile 128x32 (always in-bounds)
        #pragma unroll
        for (int i = 0; i < 4; i++) {
            int idx = tid + i * 256;
            int r = idx >> 3, c4 = (idx & 7) * 4;
            float4 v = *reinterpret_cast<const float4*>(&A[(size_t)(m0 + r) * K + k0 + c4]);
            As[r][c4 + 0] = f2tf32(v.x); As[r][c4 + 1] = f2tf32(v.y);
            As[r][c4 + 2] = f2tf32(v.z); As[r][c4 + 3] = f2tf32(v.w);
        }
        // B tile 32x128 (guard columns; all N here are multiples of 4)
        #pragma unroll
        for (int i = 0; i < 4; i++) {
            int idx = tid + i * 256;
            int kk = idx >> 5, c4 = (idx & 31) * 4;
            int col = n0 + c4;
            float4 v = make_float4(0.f, 0.f, 0.f, 0.f);
            if (col + 3 < N)
                v = *reinterpret_cast<const float4*>(&B[(size_t)(k0 + kk) * N + col]);
            Bs[kk][c4 + 0] = f2tf32(v.x); Bs[kk][c4 + 1] = f2tf32(v.y);
            Bs[kk][c4 + 2] = f2tf32(v.z); Bs[kk][c4 + 3] = f2tf32(v.w);
        }
        __syncthreads();

        #pragma unroll
        for (int ks = 0; ks < 4; ks++) {
            const int kb = ks * 8;
            uint32_t a[4][4], b[4][2];
            #pragma unroll
            for (int mt = 0; mt < 4; mt++) {
                int r = warpM * 64 + mt * 16 + gid;
                a[mt][0] = As[r][kb + tig];
                a[mt][1] = As[r + 8][kb + tig];
                a[mt][2] = As[r][kb + tig + 4];
                a[mt][3] = As[r + 8][kb + tig + 4];
            }
            #pragma unroll
            for (int nt = 0; nt < 4; nt++) {
                int cc = warpN * 32 + nt * 8 + gid;
                b[nt][0] = Bs[kb + tig][cc];
                b[nt][1] = Bs[kb + tig + 4][cc];
            }
            #pragma unroll
            for (int mt = 0; mt < 4; mt++)
                #pragma unroll
                for (int nt = 0; nt < 4; nt++)
                    mma_tf32(c[mt][nt], a[mt], b[nt]);
        }
        __syncthreads();
    }

    // epilogue: c0/c1 at (gid, 2*tig), c2/c3 at (gid+8, 2*tig)
    #pragma unroll
    for (int mt = 0; mt < 4; mt++) {
        #pragma unroll
        for (int nt = 0; nt < 4; nt++) {
            int r = m0 + warpM * 64 + mt * 16 + gid;
            int cc = n0 + warpN * 32 + nt * 8 + tig * 2;
            if (cc < N) {
                *reinterpret_cast<float2*>(&C[(size_t)r * N + cc]) =
                    make_float2(c[mt][nt][0], c[mt][nt][1]);
                *reinterpret_cast<float2*>(&C[(size_t)(r + 8) * N + cc]) =
                    make_float2(c[mt][nt][2], c[mt][nt][3]);
            }
        }
    }
}

// ---------------- rmsnorm over latent[:, :512] -------------------------------
__global__ __launch_bounds__(256) void rmsnorm_kernel(
    const float* __restrict__ latent, const float* __restrict__ w,
    float* __restrict__ out)
{
    const int t = blockIdx.x;
    const float* x = latent + (size_t)t * LATW;
    __shared__ float red[8];
    float ss = 0.f;
    for (int i = threadIdx.x; i < KV_LORA; i += 256) { float v = x[i]; ss += v * v; }
    #pragma unroll
    for (int o = 16; o > 0; o >>= 1) ss += __shfl_xor_sync(~0u, ss, o);
    if ((threadIdx.x & 31) == 0) red[threadIdx.x >> 5] = ss;
    __syncthreads();
    if (threadIdx.x == 0) {
        float v = 0.f;
        #pragma unroll
        for (int i = 0; i < 8; i++) v += red[i];
        red[0] = v;
    }
    __syncthreads();
    const float inv = rsqrtf(red[0] / (float)KV_LORA + 1e-6f);
    for (int i = threadIdx.x; i < KV_LORA; i += 256)
        out[(size_t)t * KV_LORA + i] = x[i] * inv * w[i];
}

// ---------------- non-neox RoPE ----------------------------------------------
__device__ __forceinline__ void rope_pair(float p, int i, float& x1, float& x2) {
    float inv = 1.0f / powf(10000.0f, (float)(2 * i) / (float)DR);
    float f = p * inv;
    float c = cosf(f), s = sinf(f);
    float o1 = x1 * c - x2 * s;
    float o2 = x2 * c + x1 * s;
    x1 = o1; x2 = o2;
}

__global__ __launch_bounds__(256) void rope_k_kernel(
    const float* __restrict__ latent, float* __restrict__ kpe)
{
    int idx = blockIdx.x * blockDim.x + threadIdx.x;
    if (idx >= TT * (DR / 2)) return;
    int t = idx / (DR / 2), i = idx % (DR / 2);
    float x1 = latent[(size_t)t * LATW + KV_LORA + 2 * i];
    float x2 = latent[(size_t)t * LATW + KV_LORA + 2 * i + 1];
    rope_pair((float)t, i, x1, x2);
    kpe[(size_t)t * DR + 2 * i]     = x1;
    kpe[(size_t)t * DR + 2 * i + 1] = x2;
}

__global__ __launch_bounds__(256) void rope_q_kernel(float* __restrict__ q)
{
    int idx = blockIdx.x * blockDim.x + threadIdx.x;
    if (idx >= TT * NH * (DR / 2)) return;
    int i = idx & 31;
    int h = (idx >> 5) & (NH - 1);
    int t = idx >> 9;
    float* base = q + (size_t)t * QW + h * DQ + DN;
    float x1 = base[2 * i], x2 = base[2 * i + 1];
    rope_pair((float)t, i, x1, x2);
    base[2 * i] = x1; base[2 * i + 1] = x2;
}

// ---------------- flash-style causal attention -------------------------------
#define BM 64
#define BN 64
#define ATTN_SMEM ((DQ * BM + DQ * BN + BN * DVV + BN * BM) * 4) // 147456 B

__global__ __launch_bounds__(256) void mla_attn_kernel(
    const float* __restrict__ q, const float* __restrict__ kv,
    const float* __restrict__ kpe, float* __restrict__ out)
{
    extern __shared__ float smem[];
    float* sQt = smem;               // [DQ][BM]
    float* sKt = sQt + DQ * BM;      // [DQ][BN]
    float* sV  = sKt + DQ * BN;      // [BN][DVV]
    float* sPt = sV + BN * DVV;      // [BN][BM]

    const int h = blockIdx.y;
    const int q0 = blockIdx.x * BM;
    const int tid = threadIdx.x;
    const int tx = tid & 15, ty = tid >> 4;
    const float scale = rsqrtf((float)DQ);

    for (int idx = tid; idx < BM * DQ; idx += 256) {
        int r = idx / DQ, d = idx % DQ;
        sQt[d * BM + r] = q[(size_t)(q0 + r) * QW + h * DQ + d] * scale;
    }

    float acc[4][8] = {};
    float m[4], l[4];
    #pragma unroll
    for (int i = 0; i < 4; i++) { m[i] = -1e30f; l[i] = 0.f; }

    const int jt_end = blockIdx.x;

    for (int jt = 0; jt <= jt_end; jt++) {
        const int k0 = jt * BN;
        __syncthreads();
        for (int idx = tid; idx < BN * DQ; idx += 256) {
            int r = idx / DQ, d = idx % DQ;
            float v = (d < DN) ? kv[(size_t)(k0 + r) * KVW + h * (DN + DVV) + d]
                               : kpe[(size_t)(k0 + r) * DR + (d - DN)];
            sKt[d * BN + r] = v;
        }
        for (int idx = tid; idx < BN * DVV; idx += 256) {
            int r = idx / DVV, d = idx % DVV;
            sV[r * DVV + d] = kv[(size_t)(k0 + r) * KVW + h * (DN + DVV) + DN + d];
        }
        __syncthreads();

        float s[4][4] = {};
        #pragma unroll 4
        for (int kk = 0; kk < DQ; kk++) {
            float4 a = *reinterpret_cast<const float4*>(&sQt[kk * BM + ty * 4]);
            float4 b = *reinterpret_cast<const float4*>(&sKt[kk * BN + tx * 4]);
            float av[4] = {a.x, a.y, a.z, a.w};
            float bv[4] = {b.x, b.y, b.z, b.w};
            #pragma unroll
            for (int i = 0; i < 4; i++)
                #pragma unroll
                for (int j = 0; j < 4; j++)
                    s[i][j] += av[i] * bv[j];
        }

        if (jt == jt_end) {
            #pragma unroll
            for (int i = 0; i < 4; i++) {
                int qr = ty * 4 + i;
                #pragma unroll
                for (int j = 0; j < 4; j++)
                    if (tx * 4 + j > qr) s[i][j] = -1e30f;
            }
        }

        #pragma unroll
        for (int i = 0; i < 4; i++) {
            float mx = fmaxf(fmaxf(s[i][0], s[i][1]), fmaxf(s[i][2], s[i][3]));
            #pragma unroll
            for (int o = 1; o < 16; o <<= 1) mx = fmaxf(mx, __shfl_xor_sync(~0u, mx, o));
            float mnew = fmaxf(m[i], mx);
            float alpha = __expf(m[i] - mnew);
            float rs = 0.f;
            #pragma unroll
            for (int j = 0; j < 4; j++) { s[i][j] = __expf(s[i][j] - mnew); rs += s[i][j]; }
            #pragma unroll
            for (int o = 1; o < 16; o <<= 1) rs += __shfl_xor_sync(~0u, rs, o);
            l[i] = l[i] * alpha + rs;
            m[i] = mnew;
            #pragma unroll
            for (int d = 0; d < 8; d++) acc[i][d] *= alpha;
        }

        #pragma unroll
        for (int i = 0; i < 4; i++)
            #pragma unroll
            for (int j = 0; j < 4; j++)
                sPt[(tx * 4 + j) * BM + ty * 4 + i] = s[i][j];
        __syncthreads();

        #pragma unroll 2
        for (int j = 0; j < BN; j++) {
            float4 p4 = *reinterpret_cast<const float4*>(&sPt[j * BM + ty * 4]);
            float pv[4] = {p4.x, p4.y, p4.z, p4.w};
            float4 v0 = *reinterpret_cast<const float4*>(&sV[j * DVV + tx * 8]);
            float4 v1 = *reinterpret_cast<const float4*>(&sV[j * DVV + tx * 8 + 4]);
            float vv[8] = {v0.x, v0.y, v0.z, v0.w, v1.x, v1.y, v1.z, v1.w};
            #pragma unroll
            for (int i = 0; i < 4; i++)
                #pragma unroll
                for (int d = 0; d < 8; d++)
                    acc[i][d] += pv[i] * vv[d];
        }
    }

    #pragma unroll
    for (int i = 0; i < 4; i++) {
        float inv = 1.0f / l[i];
        size_t base = (size_t)(q0 + ty * 4 + i) * (NH * DVV) + h * DVV + tx * 8;
        float4 o0 = make_float4(acc[i][0] * inv, acc[i][1] * inv, acc[i][2] * inv, acc[i][3] * inv);
        float4 o1 = make_float4(acc[i][4] * inv, acc[i][5] * inv, acc[i][6] * inv, acc[i][7] * inv);
        *reinterpret_cast<float4*>(&out[base]) = o0;
        *reinterpret_cast<float4*>(&out[base + 4]) = o1;
    }
}

// ---------------- launch ------------------------------------------------------
extern "C" void kernel_launch(void* const* d_in, const int* in_sizes, int n_in,
                              void* d_out, int out_size)
{
    const float* hidden = (const float*)d_in[1];
    const float* w_q    = (const float*)d_in[2];
    const float* w_kv_a = (const float*)d_in[3];
    const float* ln_w   = (const float*)d_in[4];
    const float* w_kv_b = (const float*)d_in[5];
    const float* w_o    = (const float*)d_in[6];
    float* out = (float*)d_out;

    float *q_p, *lat_p, *kva_p, *kpe_p, *kv_p, *attn_p;
    cudaGetSymbolAddress((void**)&q_p,    g_q);
    cudaGetSymbolAddress((void**)&lat_p,  g_latent);
    cudaGetSymbolAddress((void**)&kva_p,  g_kva);
    cudaGetSymbolAddress((void**)&kpe_p,  g_kpe);
    cudaGetSymbolAddress((void**)&kv_p,   g_kv);
    cudaGetSymbolAddress((void**)&attn_p, g_attn);

    cudaFuncSetAttribute(mla_attn_kernel,
                         cudaFuncAttributeMaxDynamicSharedMemorySize, ATTN_SMEM);

    dim3 blk(256);
    // q = hidden @ w_q  [2048 x 3072], K=2048
    gemm_tf32<<<dim3(QW / 128, TT / 128), blk>>>(hidden, w_q, q_p, TT, QW, HIDDEN);
    // latent = hidden @ w_kv_a  [2048 x 576], K=2048 (N partial tile)
    gemm_tf32<<<dim3((LATW + 127) / 128, TT / 128), blk>>>(hidden, w_kv_a, lat_p, TT, LATW, HIDDEN);
    // kv_a = rmsnorm(latent[:, :512]) * w
    rmsnorm_kernel<<<TT, 256>>>(lat_p, ln_w, kva_p);
    // k_pe = rope(latent[:, 512:])
    rope_k_kernel<<<(TT * (DR / 2) + 255) / 256, 256>>>(lat_p, kpe_p);
    // kv = kv_a @ w_kv_b  [2048 x 4096], K=512
    gemm_tf32<<<dim3(KVW / 128, TT / 128), blk>>>(kva_p, w_kv_b, kv_p, TT, KVW, KV_LORA);
    // rope q_pe in place
    rope_q_kernel<<<(TT * NH * (DR / 2) + 255) / 256, 256>>>(q_p);
    // attention
    mla_attn_kernel<<<dim3(TT / BM, NH), 256, ATTN_SMEM>>>(q_p, kv_p, kpe_p, attn_p);
    // out = attn @ w_o  [2048 x 2048], K=2048
    gemm_tf32<<<dim3(HIDDEN / 128, TT / 128), blk>>>(attn_p, w_o, out, TT, HIDDEN, NH * DVV);
}

// round 4
// speedup vs baseline: 2.6875x; 1.9251x over previous
#include <cuda_runtime.h>
#include <cuda_bf16.h>
#include <cstdint>
#include <math.h>

#define TT 2048
#define HIDDEN 2048
#define NH 16
#define DN 128
#define DR 64
#define DVV 128
#define KV_LORA 512
#define DQ (DN + DR)          // 192
#define QW (NH * DQ)          // 3072
#define KVW (NH * (DN + DVV)) // 4096
#define LATW (KV_LORA + DR)   // 576

// ---------------- scratch ----------------------------------------------------
__device__ float g_q[TT * QW];
__device__ float g_latent[TT * LATW];
__device__ float g_kva[TT * KV_LORA];
__device__ float g_kpe[TT * DR];
__device__ float g_kv[TT * KVW];
__device__ float g_attn[TT * NH * DVV];

// ---------------- tf32 helpers ------------------------------------------------
__device__ __forceinline__ uint32_t f2tf32(float x) {
    uint32_t r;
    asm("cvt.rna.tf32.f32 %0, %1;" : "=r"(r) : "f"(x));
    return r;
}

__device__ __forceinline__ void mma_tf32(float c[4], const uint32_t a[4], const uint32_t b[2]) {
    asm volatile(
        "mma.sync.aligned.m16n8k8.row.col.f32.tf32.tf32.f32 "
        "{%0,%1,%2,%3}, {%4,%5,%6,%7}, {%8,%9}, {%0,%1,%2,%3};"
        : "+f"(c[0]), "+f"(c[1]), "+f"(c[2]), "+f"(c[3])
        : "r"(a[0]), "r"(a[1]), "r"(a[2]), "r"(a[3]), "r"(b[0]), "r"(b[1]));
}

// ---------------- TF32 GEMM, double-buffered ----------------------------------
// C[M,N] = A[M,K] @ B[K,N]. Block 128x128, BK=32, 256 threads, 8 warps (64x32 each).
#define GA_STRIDE 36
#define GB_STRIDE 136
#define GA_WORDS (128 * GA_STRIDE)  // 4608
#define GB_WORDS (32 * GB_STRIDE)   // 4352
#define GEMM_SMEM ((2 * (GA_WORDS + GB_WORDS)) * 4)  // 71680 B

__global__ __launch_bounds__(256) void gemm_tf32(
    const float* __restrict__ A, const float* __restrict__ B,
    float* __restrict__ C, int M, int N, int K)
{
    extern __shared__ uint32_t gsm[];
    uint32_t* As = gsm;                 // [2][128][36]
    uint32_t* Bs = gsm + 2 * GA_WORDS;  // [2][32][136]

    const int tid  = threadIdx.x;
    const int lane = tid & 31, warp = tid >> 5;
    const int warpM = warp & 1;
    const int warpN = warp >> 1;
    const int gid = lane >> 2, tig = lane & 3;
    const int m0 = blockIdx.y * 128;
    const int n0 = blockIdx.x * 128;

    // per-thread staging coordinates
    const int ar = tid >> 3, ac = (tid & 7) * 4;     // A: rows ar+32i, cols ac..ac+3
    const int bk = tid >> 5, bc = (tid & 31) * 4;    // B: k bk+8i, cols bc..bc+3

    float4 ra[4], rb[4];

    auto ldg_tile = [&](int k0) {
        #pragma unroll
        for (int i = 0; i < 4; i++)
            ra[i] = *reinterpret_cast<const float4*>(&A[(size_t)(m0 + ar + i * 32) * K + k0 + ac]);
        #pragma unroll
        for (int i = 0; i < 4; i++) {
            int col = n0 + bc;
            rb[i] = make_float4(0.f, 0.f, 0.f, 0.f);
            if (col + 3 < N)
                rb[i] = *reinterpret_cast<const float4*>(&B[(size_t)(k0 + bk + i * 8) * N + col]);
        }
    };
    auto sts_tile = [&](int buf) {
        #pragma unroll
        for (int i = 0; i < 4; i++) {
            uint32_t* p = &As[buf * GA_WORDS + (ar + i * 32) * GA_STRIDE + ac];
            p[0] = f2tf32(ra[i].x); p[1] = f2tf32(ra[i].y);
            p[2] = f2tf32(ra[i].z); p[3] = f2tf32(ra[i].w);
        }
        #pragma unroll
        for (int i = 0; i < 4; i++) {
            uint32_t* p = &Bs[buf * GB_WORDS + (bk + i * 8) * GB_STRIDE + bc];
            p[0] = f2tf32(rb[i].x); p[1] = f2tf32(rb[i].y);
            p[2] = f2tf32(rb[i].z); p[3] = f2tf32(rb[i].w);
        }
    };

    float c[4][4][4] = {};

    ldg_tile(0);
    sts_tile(0);
    __syncthreads();

    int buf = 0;
    for (int k0 = 0; k0 < K; k0 += 32) {
        const bool has_next = (k0 + 32 < K);
        if (has_next) ldg_tile(k0 + 32);

        const uint32_t* Ab = &As[buf * GA_WORDS];
        const uint32_t* Bb = &Bs[buf * GB_WORDS];
        #pragma unroll
        for (int ks = 0; ks < 4; ks++) {
            const int kb = ks * 8;
            uint32_t a[4][4], b[4][2];
            #pragma unroll
            for (int mt = 0; mt < 4; mt++) {
                int r = warpM * 64 + mt * 16 + gid;
                a[mt][0] = Ab[r * GA_STRIDE + kb + tig];
                a[mt][1] = Ab[(r + 8) * GA_STRIDE + kb + tig];
                a[mt][2] = Ab[r * GA_STRIDE + kb + tig + 4];
                a[mt][3] = Ab[(r + 8) * GA_STRIDE + kb + tig + 4];
            }
            #pragma unroll
            for (int nt = 0; nt < 4; nt++) {
                int cc = warpN * 32 + nt * 8 + gid;
                b[nt][0] = Bb[(kb + tig) * GB_STRIDE + cc];
                b[nt][1] = Bb[(kb + tig + 4) * GB_STRIDE + cc];
            }
            #pragma unroll
            for (int mt = 0; mt < 4; mt++)
                #pragma unroll
                for (int nt = 0; nt < 4; nt++)
                    mma_tf32(c[mt][nt], a[mt], b[nt]);
        }

        if (has_next) {
            sts_tile(buf ^ 1);
            __syncthreads();
            buf ^= 1;
        }
    }

    #pragma unroll
    for (int mt = 0; mt < 4; mt++) {
        #pragma unroll
        for (int nt = 0; nt < 4; nt++) {
            int r = m0 + warpM * 64 + mt * 16 + gid;
            int cc = n0 + warpN * 32 + nt * 8 + tig * 2;
            if (cc < N) {
                *reinterpret_cast<float2*>(&C[(size_t)r * N + cc]) =
                    make_float2(c[mt][nt][0], c[mt][nt][1]);
                *reinterpret_cast<float2*>(&C[(size_t)(r + 8) * N + cc]) =
                    make_float2(c[mt][nt][2], c[mt][nt][3]);
            }
        }
    }
}

// ---------------- rmsnorm -----------------------------------------------------
__global__ __launch_bounds__(256) void rmsnorm_kernel(
    const float* __restrict__ latent, const float* __restrict__ w,
    float* __restrict__ out)
{
    const int t = blockIdx.x;
    const float* x = latent + (size_t)t * LATW;
    __shared__ float red[8];
    float ss = 0.f;
    for (int i = threadIdx.x; i < KV_LORA; i += 256) { float v = x[i]; ss += v * v; }
    #pragma unroll
    for (int o = 16; o > 0; o >>= 1) ss += __shfl_xor_sync(~0u, ss, o);
    if ((threadIdx.x & 31) == 0) red[threadIdx.x >> 5] = ss;
    __syncthreads();
    if (threadIdx.x == 0) {
        float v = 0.f;
        #pragma unroll
        for (int i = 0; i < 8; i++) v += red[i];
        red[0] = v;
    }
    __syncthreads();
    const float inv = rsqrtf(red[0] / (float)KV_LORA + 1e-6f);
    for (int i = threadIdx.x; i < KV_LORA; i += 256)
        out[(size_t)t * KV_LORA + i] = x[i] * inv * w[i];
}

// ---------------- non-neox RoPE ------------------------------------------------
__device__ __forceinline__ void rope_pair(float p, int i, float& x1, float& x2) {
    float inv = 1.0f / powf(10000.0f, (float)(2 * i) / (float)DR);
    float f = p * inv;
    float c = cosf(f), s = sinf(f);
    float o1 = x1 * c - x2 * s;
    float o2 = x2 * c + x1 * s;
    x1 = o1; x2 = o2;
}

__global__ __launch_bounds__(256) void rope_k_kernel(
    const float* __restrict__ latent, float* __restrict__ kpe)
{
    int idx = blockIdx.x * blockDim.x + threadIdx.x;
    if (idx >= TT * (DR / 2)) return;
    int t = idx / (DR / 2), i = idx % (DR / 2);
    float x1 = latent[(size_t)t * LATW + KV_LORA + 2 * i];
    float x2 = latent[(size_t)t * LATW + KV_LORA + 2 * i + 1];
    rope_pair((float)t, i, x1, x2);
    kpe[(size_t)t * DR + 2 * i]     = x1;
    kpe[(size_t)t * DR + 2 * i + 1] = x2;
}

__global__ __launch_bounds__(256) void rope_q_kernel(float* __restrict__ q)
{
    int idx = blockIdx.x * blockDim.x + threadIdx.x;
    if (idx >= TT * NH * (DR / 2)) return;
    int i = idx & 31;
    int h = (idx >> 5) & (NH - 1);
    int t = idx >> 9;
    float* base = q + (size_t)t * QW + h * DQ + DN;
    float x1 = base[2 * i], x2 = base[2 * i + 1];
    rope_pair((float)t, i, x1, x2);
    base[2 * i] = x1; base[2 * i + 1] = x2;
}

// ---------------- tensor-core flash attention ----------------------------------
// BM=128 q rows per CTA, BN=64 keys per tile, 256 threads (8 warps x 16 rows).
#define ABM 128
#define ABN 64
#define DQP (DQ + 4)    // 196
#define DVP (DVV + 4)   // 132
#define BNP (ABN + 4)   // 68
#define ATTN_WORDS (ABM * DQP + ABN * DQP + ABN * DVP + ABM * BNP)
#define ATTN_SMEM (ATTN_WORDS * 4)   // 219136 B

__global__ __launch_bounds__(256) void mla_attn_tc(
    const float* __restrict__ q, const float* __restrict__ kv,
    const float* __restrict__ kpe, float* __restrict__ out)
{
    extern __shared__ uint32_t asm_[];
    uint32_t* sQ = asm_;                  // [ABM][DQP] tf32, pre-scaled
    uint32_t* sK = sQ + ABM * DQP;        // [ABN][DQP] tf32
    uint32_t* sV = sK + ABN * DQP;        // [ABN][DVP] tf32
    uint32_t* sP = sV + ABN * DVP;        // [ABM][BNP] tf32

    const int h  = blockIdx.y;
    const int bx = blockIdx.x;
    const int q0 = bx * ABM;
    const int tid = threadIdx.x;
    const int lane = tid & 31, warp = tid >> 5;
    const int gid = lane >> 2, tig = lane & 3;
    const int r0 = warp * 16;              // warp's row slab within tile
    const float scale = rsqrtf((float)DQ);

    // Q tile: [ABM][DQ], scaled + tf32
    for (int idx = tid; idx < ABM * DQ; idx += 256) {
        int r = idx / DQ, d = idx % DQ;
        sQ[r * DQP + d] = f2tf32(q[(size_t)(q0 + r) * QW + h * DQ + d] * scale);
    }

    float o[16][4] = {};
    float m_a = -1e30f, m_b = -1e30f, l_a = 0.f, l_b = 0.f;

    const int jt_end = 2 * bx + 1;

    for (int jt = 0; jt <= jt_end; jt++) {
        const int k0 = jt * ABN;
        __syncthreads(); // all warps done with previous sK/sV (and sQ writes on jt=0)

        for (int idx = tid; idx < ABN * DQ; idx += 256) {
            int r = idx / DQ, d = idx % DQ;
            float v = (d < DN) ? kv[(size_t)(k0 + r) * KVW + h * (DN + DVV) + d]
                               : kpe[(size_t)(k0 + r) * DR + (d - DN)];
            sK[r * DQP + d] = f2tf32(v);
        }
        for (int idx = tid; idx < ABN * DVV; idx += 256) {
            int r = idx / DVV, d = idx % DVV;
            sV[r * DVP + d] = f2tf32(kv[(size_t)(k0 + r) * KVW + h * (DN + DVV) + DN + d]);
        }
        __syncthreads();

        // ---- scores S[16][64] per warp: 8 n-tiles of m16n8, K over DQ=192 ----
        float s[8][4] = {};
        #pragma unroll 6
        for (int kb = 0; kb < DQ; kb += 8) {
            uint32_t a[4];
            a[0] = sQ[(r0 + gid) * DQP + kb + tig];
            a[1] = sQ[(r0 + gid + 8) * DQP + kb + tig];
            a[2] = sQ[(r0 + gid) * DQP + kb + tig + 4];
            a[3] = sQ[(r0 + gid + 8) * DQP + kb + tig + 4];
            #pragma unroll
            for (int nt = 0; nt < 8; nt++) {
                uint32_t b[2];
                b[0] = sK[(nt * 8 + gid) * DQP + kb + tig];
                b[1] = sK[(nt * 8 + gid) * DQP + kb + tig + 4];
                mma_tf32(s[nt], a, b);
            }
        }

        // causal mask (only needed on the last two tiles)
        if (jt >= 2 * bx) {
            const int rowA = q0 + r0 + gid;
            const int rowB = rowA + 8;
            #pragma unroll
            for (int nt = 0; nt < 8; nt++) {
                int c0 = k0 + nt * 8 + tig * 2;
                if (c0 > rowA)     s[nt][0] = -1e30f;
                if (c0 + 1 > rowA) s[nt][1] = -1e30f;
                if (c0 > rowB)     s[nt][2] = -1e30f;
                if (c0 + 1 > rowB) s[nt][3] = -1e30f;
            }
        }

        // ---- online softmax: rows A=(r0+gid), B=(r0+gid+8); 4 lanes per row ----
        float mxa = -1e30f, mxb = -1e30f;
        #pragma unroll
        for (int nt = 0; nt < 8; nt++) {
            mxa = fmaxf(mxa, fmaxf(s[nt][0], s[nt][1]));
            mxb = fmaxf(mxb, fmaxf(s[nt][2], s[nt][3]));
        }
        mxa = fmaxf(mxa, __shfl_xor_sync(~0u, mxa, 1));
        mxa = fmaxf(mxa, __shfl_xor_sync(~0u, mxa, 2));
        mxb = fmaxf(mxb, __shfl_xor_sync(~0u, mxb, 1));
        mxb = fmaxf(mxb, __shfl_xor_sync(~0u, mxb, 2));

        float mna = fmaxf(m_a, mxa), mnb = fmaxf(m_b, mxb);
        float alpha_a = __expf(m_a - mna), alpha_b = __expf(m_b - mnb);
        float sa = 0.f, sb = 0.f;
        #pragma unroll
        for (int nt = 0; nt < 8; nt++) {
            s[nt][0] = __expf(s[nt][0] - mna);
            s[nt][1] = __expf(s[nt][1] - mna);
            s[nt][2] = __expf(s[nt][2] - mnb);
            s[nt][3] = __expf(s[nt][3] - mnb);
            sa += s[nt][0] + s[nt][1];
            sb += s[nt][2] + s[nt][3];
        }
        sa += __shfl_xor_sync(~0u, sa, 1); sa += __shfl_xor_sync(~0u, sa, 2);
        sb += __shfl_xor_sync(~0u, sb, 1); sb += __shfl_xor_sync(~0u, sb, 2);
        l_a = l_a * alpha_a + sa;
        l_b = l_b * alpha_b + sb;
        m_a = mna; m_b = mnb;

        #pragma unroll
        for (int nt = 0; nt < 16; nt++) {
            o[nt][0] *= alpha_a; o[nt][1] *= alpha_a;
            o[nt][2] *= alpha_b; o[nt][3] *= alpha_b;
        }

        // ---- stash P (tf32) in sP; each warp owns its 16 rows ----
        #pragma unroll
        for (int nt = 0; nt < 8; nt++) {
            sP[(r0 + gid) * BNP + nt * 8 + tig * 2]     = f2tf32(s[nt][0]);
            sP[(r0 + gid) * BNP + nt * 8 + tig * 2 + 1] = f2tf32(s[nt][1]);
            sP[(r0 + gid + 8) * BNP + nt * 8 + tig * 2]     = f2tf32(s[nt][2]);
            sP[(r0 + gid + 8) * BNP + nt * 8 + tig * 2 + 1] = f2tf32(s[nt][3]);
        }
        __syncwarp();

        // ---- O += P @ V : K over 64 keys, 16 n-tiles over DVV=128 ----
        #pragma unroll
        for (int kb = 0; kb < ABN; kb += 8) {
            uint32_t a[4];
            a[0] = sP[(r0 + gid) * BNP + kb + tig];
            a[1] = sP[(r0 + gid + 8) * BNP + kb + tig];
            a[2] = sP[(r0 + gid) * BNP + kb + tig + 4];
            a[3] = sP[(r0 + gid + 8) * BNP + kb + tig + 4];
            #pragma unroll
            for (int nt = 0; nt < 16; nt++) {
                uint32_t b[2];
                b[0] = sV[(kb + tig) * DVP + nt * 8 + gid];
                b[1] = sV[(kb + tig + 4) * DVP + nt * 8 + gid];
                mma_tf32(o[nt], a, b);
            }
        }
    }

    const float inv_a = 1.0f / l_a, inv_b = 1.0f / l_b;
    const int rowA = q0 + r0 + gid, rowB = rowA + 8;
    #pragma unroll
    for (int nt = 0; nt < 16; nt++) {
        int cc = h * DVV + nt * 8 + tig * 2;
        *reinterpret_cast<float2*>(&out[(size_t)rowA * (NH * DVV) + cc]) =
            make_float2(o[nt][0] * inv_a, o[nt][1] * inv_a);
        *reinterpret_cast<float2*>(&out[(size_t)rowB * (NH * DVV) + cc]) =
            make_float2(o[nt][2] * inv_b, o[nt][3] * inv_b);
    }
}

// ---------------- launch --------------------------------------------------------
extern "C" void kernel_launch(void* const* d_in, const int* in_sizes, int n_in,
                              void* d_out, int out_size)
{
    const float* hidden = (const float*)d_in[1];
    const float* w_q    = (const float*)d_in[2];
    const float* w_kv_a = (const float*)d_in[3];
    const float* ln_w   = (const float*)d_in[4];
    const float* w_kv_b = (const float*)d_in[5];
    const float* w_o    = (const float*)d_in[6];
    float* out = (float*)d_out;

    float *q_p, *lat_p, *kva_p, *kpe_p, *kv_p, *attn_p;
    cudaGetSymbolAddress((void**)&q_p,    g_q);
    cudaGetSymbolAddress((void**)&lat_p,  g_latent);
    cudaGetSymbolAddress((void**)&kva_p,  g_kva);
    cudaGetSymbolAddress((void**)&kpe_p,  g_kpe);
    cudaGetSymbolAddress((void**)&kv_p,   g_kv);
    cudaGetSymbolAddress((void**)&attn_p, g_attn);

    cudaFuncSetAttribute(gemm_tf32,
                         cudaFuncAttributeMaxDynamicSharedMemorySize, GEMM_SMEM);
    cudaFuncSetAttribute(mla_attn_tc,
                         cudaFuncAttributeMaxDynamicSharedMemorySize, ATTN_SMEM);

    dim3 blk(256);
    gemm_tf32<<<dim3(QW / 128, TT / 128), blk, GEMM_SMEM>>>(hidden, w_q, q_p, TT, QW, HIDDEN);
    gemm_tf32<<<dim3((LATW + 127) / 128, TT / 128), blk, GEMM_SMEM>>>(hidden, w_kv_a, lat_p, TT, LATW, HIDDEN);
    rmsnorm_kernel<<<TT, 256>>>(lat_p, ln_w, kva_p);
    rope_k_kernel<<<(TT * (DR / 2) + 255) / 256, 256>>>(lat_p, kpe_p);
    gemm_tf32<<<dim3(KVW / 128, TT / 128), blk, GEMM_SMEM>>>(kva_p, w_kv_b, kv_p, TT, KVW, KV_LORA);
    rope_q_kernel<<<(TT * NH * (DR / 2) + 255) / 256, 256>>>(q_p);
    mla_attn_tc<<<dim3(TT / ABM, NH), blk, ATTN_SMEM>>>(q_p, kv_p, kpe_p, attn_p);
    gemm_tf32<<<dim3(HIDDEN / 128, TT / 128), blk, GEMM_SMEM>>>(attn_p, w_o, out, TT, HIDDEN, NH * DVV);
}

// round 5
// speedup vs baseline: 3.7125x; 1.3814x over previous
#include <cuda_runtime.h>
#include <cuda_bf16.h>
#include <cstdint>
#include <math.h>

#define TT 2048
#define HIDDEN 2048
#define NH 16
#define DN 128
#define DR 64
#define DVV 128
#define KV_LORA 512
#define DQ (DN + DR)          // 192
#define QW (NH * DQ)          // 3072
#define KVW (NH * (DN + DVV)) // 4096
#define LATW (KV_LORA + DR)   // 576

// ---------------- scratch ----------------------------------------------------
__device__ float g_q[TT * QW];
__device__ float g_latent[TT * LATW];
__device__ float g_kva[TT * KV_LORA];
__device__ float g_kpe[TT * DR];
__device__ float g_kv[TT * KVW];
__device__ float g_attn[TT * NH * DVV];

// ---------------- helpers -----------------------------------------------------
__device__ __forceinline__ uint32_t f2tf32(float x) {
    uint32_t r;
    asm("cvt.rna.tf32.f32 %0, %1;" : "=r"(r) : "f"(x));
    return r;
}

__device__ __forceinline__ void mma_tf32(float c[4], const uint32_t a[4], const uint32_t b[2]) {
    asm volatile(
        "mma.sync.aligned.m16n8k8.row.col.f32.tf32.tf32.f32 "
        "{%0,%1,%2,%3}, {%4,%5,%6,%7}, {%8,%9}, {%0,%1,%2,%3};"
        : "+f"(c[0]), "+f"(c[1]), "+f"(c[2]), "+f"(c[3])
        : "r"(a[0]), "r"(a[1]), "r"(a[2]), "r"(a[3]), "r"(b[0]), "r"(b[1]));
}

__device__ __forceinline__ uint32_t smem_u32(const void* p) {
    return (uint32_t)__cvta_generic_to_shared(p);
}

__device__ __forceinline__ void cp16(uint32_t dst, const void* src, int src_bytes) {
    asm volatile("cp.async.cg.shared.global [%0], [%1], 16, %2;"
                 :: "r"(dst), "l"(src), "r"(src_bytes));
}
#define CP_COMMIT() asm volatile("cp.async.commit_group;")
#define CP_WAIT(n)  asm volatile("cp.async.wait_group %0;" :: "n"(n))

// ---------------- TF32 GEMM, 4-stage cp.async pipeline -------------------------
// C[M,N] = A[M,K] @ B[K,N]. Block 128x128, BK=32, 256 threads, 8 warps (64x32).
#define GSTAGES 4
#define GA_STRIDE 36
#define GB_STRIDE 136
#define GAW (128 * GA_STRIDE)          // 4608 words
#define GBW (32 * GB_STRIDE)           // 4352 words
#define GSTAGE_W (GAW + GBW)           // 8960 words
#define GEMM_SMEM (GSTAGES * GSTAGE_W * 4)  // 143360 B

__global__ __launch_bounds__(256) void gemm_tf32(
    const float* __restrict__ A, const float* __restrict__ B,
    float* __restrict__ C, int M, int N, int K)
{
    extern __shared__ float gsm[];
    const uint32_t smBase = smem_u32(gsm);

    const int tid  = threadIdx.x;
    const int lane = tid & 31, warp = tid >> 5;
    const int warpM = warp & 1;
    const int warpN = warp >> 1;
    const int gid = lane >> 2, tig = lane & 3;
    const int m0 = blockIdx.y * 128;
    const int n0 = blockIdx.x * 128;

    const int ar = tid >> 3, ac = (tid & 7) * 4;   // A: rows ar+32i, cols ac..ac+3
    const int bk = tid >> 5, bc = (tid & 31) * 4;  // B: k rows bk+8i, cols bc..bc+3

    const int nslab = K >> 5;

    auto issue_slab = [&](int slab) {
        const int k0 = slab * 32;
        const uint32_t stg = smBase + (uint32_t)((slab & (GSTAGES - 1)) * GSTAGE_W) * 4;
        #pragma unroll
        for (int i = 0; i < 4; i++) {
            uint32_t dst = stg + (uint32_t)((ar + 32 * i) * GA_STRIDE + ac) * 4;
            cp16(dst, &A[(size_t)(m0 + ar + 32 * i) * K + k0 + ac], 16);
        }
        #pragma unroll
        for (int i = 0; i < 4; i++) {
            uint32_t dst = stg + (uint32_t)(GAW + (bk + 8 * i) * GB_STRIDE + bc) * 4;
            int col = n0 + bc;
            cp16(dst, &B[(size_t)(k0 + bk + 8 * i) * N + col], (col < N) ? 16 : 0);
        }
    };

    // prologue: stages 0..2
    #pragma unroll
    for (int s = 0; s < GSTAGES - 1; s++) {
        if (s < nslab) issue_slab(s);
        CP_COMMIT();
    }

    float c[4][4][4] = {};

    for (int i = 0; i < nslab; i++) {
        CP_WAIT(GSTAGES - 2);   // slab i landed
        __syncthreads();         // visible to all; buffer (i-1)%4 free

        if (i + GSTAGES - 1 < nslab) issue_slab(i + GSTAGES - 1);
        CP_COMMIT();             // unconditional: keeps group counting uniform

        const float* Ab = gsm + (i & (GSTAGES - 1)) * GSTAGE_W;
        const float* Bb = Ab + GAW;

        #pragma unroll
        for (int ks = 0; ks < 4; ks++) {
            const int kb = ks * 8;
            uint32_t a[4][4], b[4][2];
            #pragma unroll
            for (int mt = 0; mt < 4; mt++) {
                int r = warpM * 64 + mt * 16 + gid;
                a[mt][0] = f2tf32(Ab[r * GA_STRIDE + kb + tig]);
                a[mt][1] = f2tf32(Ab[(r + 8) * GA_STRIDE + kb + tig]);
                a[mt][2] = f2tf32(Ab[r * GA_STRIDE + kb + tig + 4]);
                a[mt][3] = f2tf32(Ab[(r + 8) * GA_STRIDE + kb + tig + 4]);
            }
            #pragma unroll
            for (int nt = 0; nt < 4; nt++) {
                int cc = warpN * 32 + nt * 8 + gid;
                b[nt][0] = f2tf32(Bb[(kb + tig) * GB_STRIDE + cc]);
                b[nt][1] = f2tf32(Bb[(kb + tig + 4) * GB_STRIDE + cc]);
            }
            #pragma unroll
            for (int mt = 0; mt < 4; mt++)
                #pragma unroll
                for (int nt = 0; nt < 4; nt++)
                    mma_tf32(c[mt][nt], a[mt], b[nt]);
        }
    }

    #pragma unroll
    for (int mt = 0; mt < 4; mt++) {
        #pragma unroll
        for (int nt = 0; nt < 4; nt++) {
            int r = m0 + warpM * 64 + mt * 16 + gid;
            int cc = n0 + warpN * 32 + nt * 8 + tig * 2;
            if (cc < N) {
                *reinterpret_cast<float2*>(&C[(size_t)r * N + cc]) =
                    make_float2(c[mt][nt][0], c[mt][nt][1]);
                *reinterpret_cast<float2*>(&C[(size_t)(r + 8) * N + cc]) =
                    make_float2(c[mt][nt][2], c[mt][nt][3]);
            }
        }
    }
}

// ---------------- rmsnorm -----------------------------------------------------
__global__ __launch_bounds__(256) void rmsnorm_kernel(
    const float* __restrict__ latent, const float* __restrict__ w,
    float* __restrict__ out)
{
    const int t = blockIdx.x;
    const float* x = latent + (size_t)t * LATW;
    __shared__ float red[8];
    float ss = 0.f;
    for (int i = threadIdx.x; i < KV_LORA; i += 256) { float v = x[i]; ss += v * v; }
    #pragma unroll
    for (int o = 16; o > 0; o >>= 1) ss += __shfl_xor_sync(~0u, ss, o);
    if ((threadIdx.x & 31) == 0) red[threadIdx.x >> 5] = ss;
    __syncthreads();
    if (threadIdx.x == 0) {
        float v = 0.f;
        #pragma unroll
        for (int i = 0; i < 8; i++) v += red[i];
        red[0] = v;
    }
    __syncthreads();
    const float inv = rsqrtf(red[0] / (float)KV_LORA + 1e-6f);
    for (int i = threadIdx.x; i < KV_LORA; i += 256)
        out[(size_t)t * KV_LORA + i] = x[i] * inv * w[i];
}

// ---------------- non-neox RoPE ------------------------------------------------
__device__ __forceinline__ void rope_pair(float p, int i, float& x1, float& x2) {
    float inv = 1.0f / powf(10000.0f, (float)(2 * i) / (float)DR);
    float f = p * inv;
    float c = cosf(f), s = sinf(f);
    float o1 = x1 * c - x2 * s;
    float o2 = x2 * c + x1 * s;
    x1 = o1; x2 = o2;
}

__global__ __launch_bounds__(256) void rope_k_kernel(
    const float* __restrict__ latent, float* __restrict__ kpe)
{
    int idx = blockIdx.x * blockDim.x + threadIdx.x;
    if (idx >= TT * (DR / 2)) return;
    int t = idx / (DR / 2), i = idx % (DR / 2);
    float x1 = latent[(size_t)t * LATW + KV_LORA + 2 * i];
    float x2 = latent[(size_t)t * LATW + KV_LORA + 2 * i + 1];
    rope_pair((float)t, i, x1, x2);
    kpe[(size_t)t * DR + 2 * i]     = x1;
    kpe[(size_t)t * DR + 2 * i + 1] = x2;
}

__global__ __launch_bounds__(256) void rope_q_kernel(float* __restrict__ q)
{
    int idx = blockIdx.x * blockDim.x + threadIdx.x;
    if (idx >= TT * NH * (DR / 2)) return;
    int i = idx & 31;
    int h = (idx >> 5) & (NH - 1);
    int t = idx >> 9;
    float* base = q + (size_t)t * QW + h * DQ + DN;
    float x1 = base[2 * i], x2 = base[2 * i + 1];
    rope_pair((float)t, i, x1, x2);
    base[2 * i] = x1; base[2 * i + 1] = x2;
}

// ---------------- tensor-core flash attention with cp.async overlap ------------
#define ABM 128
#define ABN 64
#define DQP (DQ + 4)    // 196
#define DVP (DVV + 4)   // 132
#define BNP (ABN + 4)   // 68
#define SQ_W (ABM * DQP)   // 25088
#define SK_W (ABN * DQP)   // 12544
#define SV_W (ABN * DVP)   // 8448
#define SP_W (ABM * BNP)   // 8704
#define ATTN_SMEM ((SQ_W + SK_W + SV_W + SP_W) * 4)  // 219136 B

__global__ __launch_bounds__(256) void mla_attn_tc(
    const float* __restrict__ q, const float* __restrict__ kv,
    const float* __restrict__ kpe, float* __restrict__ out)
{
    extern __shared__ uint32_t asm_[];
    uint32_t* sQ  = asm_;                       // tf32
    float*    sKf = (float*)(asm_ + SQ_W);      // raw fp32 -> tf32 in place
    float*    sVf = (float*)(asm_ + SQ_W + SK_W);
    uint32_t* sP  = asm_ + SQ_W + SK_W + SV_W;  // tf32
    uint32_t* sKu = (uint32_t*)sKf;
    uint32_t* sVu = (uint32_t*)sVf;
    const uint32_t sKb = smem_u32(sKf);
    const uint32_t sVb = smem_u32(sVf);

    const int h  = blockIdx.y;
    const int bx = blockIdx.x;
    const int q0 = bx * ABM;
    const int tid = threadIdx.x;
    const int lane = tid & 31, warp = tid >> 5;
    const int gid = lane >> 2, tig = lane & 3;
    const int r0 = warp * 16;
    const float scale = rsqrtf((float)DQ);

    auto issueK = [&](int k0) {
        #pragma unroll
        for (int j = 0; j < 12; j++) {     // 64*192/4 = 3072 chunks / 256 thr
            int c = j * 256 + tid;
            int r = c / 48, col4 = (c % 48) * 4;
            uint32_t dst = sKb + (uint32_t)(r * DQP + col4) * 4;
            const float* src = (col4 < DN)
                ? &kv[(size_t)(k0 + r) * KVW + h * (DN + DVV) + col4]
                : &kpe[(size_t)(k0 + r) * DR + (col4 - DN)];
            cp16(dst, src, 16);
        }
    };
    auto issueV = [&](int k0) {
        #pragma unroll
        for (int j = 0; j < 8; j++) {      // 64*128/4 = 2048 chunks / 256 thr
            int c = j * 256 + tid;
            int r = c / 32, col4 = (c % 32) * 4;
            uint32_t dst = sVb + (uint32_t)(r * DVP + col4) * 4;
            cp16(dst, &kv[(size_t)(k0 + r) * KVW + h * (DN + DVV) + DN + col4], 16);
        }
    };

    // prefetch K(0), overlap with Q staging
    issueK(0);
    CP_COMMIT();

    for (int idx = tid; idx < ABM * DQ; idx += 256) {
        int r = idx / DQ, d = idx % DQ;
        sQ[r * DQP + d] = f2tf32(q[(size_t)(q0 + r) * QW + h * DQ + d] * scale);
    }

    float o[16][4] = {};
    float m_a = -1e30f, m_b = -1e30f, l_a = 0.f, l_b = 0.f;
    const int jt_end = 2 * bx + 1;

    for (int jt = 0; jt <= jt_end; jt++) {
        const int k0 = jt * ABN;

        CP_WAIT(0);        // K(jt) landed (V(jt-1) drained earlier)
        __syncthreads();   // K visible; all warps done with sV/sK of prev tile

        issueV(k0);        // V load overlaps K-convert + S-mma
        CP_COMMIT();

        // convert K to tf32 in place (own chunks only)
        #pragma unroll
        for (int j = 0; j < 12; j++) {
            int c = j * 256 + tid;
            int r = c / 48, col4 = (c % 48) * 4;
            float4 v = *reinterpret_cast<const float4*>(&sKf[r * DQP + col4]);
            uint32_t* p = &sKu[r * DQP + col4];
            p[0] = f2tf32(v.x); p[1] = f2tf32(v.y);
            p[2] = f2tf32(v.z); p[3] = f2tf32(v.w);
        }
        __syncthreads();   // K(tf32) visible

        // ---- S = Q @ K^T ----
        float s[8][4] = {};
        #pragma unroll 6
        for (int kb = 0; kb < DQ; kb += 8) {
            uint32_t a[4];
            a[0] = sQ[(r0 + gid) * DQP + kb + tig];
            a[1] = sQ[(r0 + gid + 8) * DQP + kb + tig];
            a[2] = sQ[(r0 + gid) * DQP + kb + tig + 4];
            a[3] = sQ[(r0 + gid + 8) * DQP + kb + tig + 4];
            #pragma unroll
            for (int nt = 0; nt < 8; nt++) {
                uint32_t b[2];
                b[0] = sKu[(nt * 8 + gid) * DQP + kb + tig];
                b[1] = sKu[(nt * 8 + gid) * DQP + kb + tig + 4];
                mma_tf32(s[nt], a, b);
            }
        }
        __syncthreads();   // all warps done reading sK -> safe to refill

        if (jt < jt_end) { // K(jt+1) load overlaps softmax + PV
            issueK(k0 + ABN);
            CP_COMMIT();
        }

        // causal mask
        if (jt >= 2 * bx) {
            const int rowA = q0 + r0 + gid;
            const int rowB = rowA + 8;
            #pragma unroll
            for (int nt = 0; nt < 8; nt++) {
                int c0 = k0 + nt * 8 + tig * 2;
                if (c0 > rowA)     s[nt][0] = -1e30f;
                if (c0 + 1 > rowA) s[nt][1] = -1e30f;
                if (c0 > rowB)     s[nt][2] = -1e30f;
                if (c0 + 1 > rowB) s[nt][3] = -1e30f;
            }
        }

        // ---- online softmax ----
        float mxa = -1e30f, mxb = -1e30f;
        #pragma unroll
        for (int nt = 0; nt < 8; nt++) {
            mxa = fmaxf(mxa, fmaxf(s[nt][0], s[nt][1]));
            mxb = fmaxf(mxb, fmaxf(s[nt][2], s[nt][3]));
        }
        mxa = fmaxf(mxa, __shfl_xor_sync(~0u, mxa, 1));
        mxa = fmaxf(mxa, __shfl_xor_sync(~0u, mxa, 2));
        mxb = fmaxf(mxb, __shfl_xor_sync(~0u, mxb, 1));
        mxb = fmaxf(mxb, __shfl_xor_sync(~0u, mxb, 2));

        float mna = fmaxf(m_a, mxa), mnb = fmaxf(m_b, mxb);
        float alpha_a = __expf(m_a - mna), alpha_b = __expf(m_b - mnb);
        float sa = 0.f, sb = 0.f;
        #pragma unroll
        for (int nt = 0; nt < 8; nt++) {
            s[nt][0] = __expf(s[nt][0] - mna);
            s[nt][1] = __expf(s[nt][1] - mna);
            s[nt][2] = __expf(s[nt][2] - mnb);
            s[nt][3] = __expf(s[nt][3] - mnb);
            sa += s[nt][0] + s[nt][1];
            sb += s[nt][2] + s[nt][3];
        }
        sa += __shfl_xor_sync(~0u, sa, 1); sa += __shfl_xor_sync(~0u, sa, 2);
        sb += __shfl_xor_sync(~0u, sb, 1); sb += __shfl_xor_sync(~0u, sb, 2);
        l_a = l_a * alpha_a + sa;
        l_b = l_b * alpha_b + sb;
        m_a = mna; m_b = mnb;

        #pragma unroll
        for (int nt = 0; nt < 16; nt++) {
            o[nt][0] *= alpha_a; o[nt][1] *= alpha_a;
            o[nt][2] *= alpha_b; o[nt][3] *= alpha_b;
        }

        // wait V(jt) (K(jt+1) may still be in flight)
        if (jt < jt_end) { CP_WAIT(1); } else { CP_WAIT(0); }
        __syncthreads();   // V visible

        // convert V in place (own chunks)
        #pragma unroll
        for (int j = 0; j < 8; j++) {
            int c = j * 256 + tid;
            int r = c / 32, col4 = (c % 32) * 4;
            float4 v = *reinterpret_cast<const float4*>(&sVf[r * DVP + col4]);
            uint32_t* p = &sVu[r * DVP + col4];
            p[0] = f2tf32(v.x); p[1] = f2tf32(v.y);
            p[2] = f2tf32(v.z); p[3] = f2tf32(v.w);
        }

        // stash P (tf32)
        #pragma unroll
        for (int nt = 0; nt < 8; nt++) {
            sP[(r0 + gid) * BNP + nt * 8 + tig * 2]         = f2tf32(s[nt][0]);
            sP[(r0 + gid) * BNP + nt * 8 + tig * 2 + 1]     = f2tf32(s[nt][1]);
            sP[(r0 + gid + 8) * BNP + nt * 8 + tig * 2]     = f2tf32(s[nt][2]);
            sP[(r0 + gid + 8) * BNP + nt * 8 + tig * 2 + 1] = f2tf32(s[nt][3]);
        }
        __syncthreads();   // V(tf32) visible (covers sP too)

        // ---- O += P @ V ----
        #pragma unroll
        for (int kb = 0; kb < ABN; kb += 8) {
            uint32_t a[4];
            a[0] = sP[(r0 + gid) * BNP + kb + tig];
            a[1] = sP[(r0 + gid + 8) * BNP + kb + tig];
            a[2] = sP[(r0 + gid) * BNP + kb + tig + 4];
            a[3] = sP[(r0 + gid + 8) * BNP + kb + tig + 4];
            #pragma unroll
            for (int nt = 0; nt < 16; nt++) {
                uint32_t b[2];
                b[0] = sVu[(kb + tig) * DVP + nt * 8 + gid];
                b[1] = sVu[(kb + tig + 4) * DVP + nt * 8 + gid];
                mma_tf32(o[nt], a, b);
            }
        }
    }

    const float inv_a = 1.0f / l_a, inv_b = 1.0f / l_b;
    const int rowA = q0 + r0 + gid, rowB = rowA + 8;
    #pragma unroll
    for (int nt = 0; nt < 16; nt++) {
        int cc = h * DVV + nt * 8 + tig * 2;
        *reinterpret_cast<float2*>(&out[(size_t)rowA * (NH * DVV) + cc]) =
            make_float2(o[nt][0] * inv_a, o[nt][1] * inv_a);
        *reinterpret_cast<float2*>(&out[(size_t)rowB * (NH * DVV) + cc]) =
            make_float2(o[nt][2] * inv_b, o[nt][3] * inv_b);
    }
}

// ---------------- launch --------------------------------------------------------
extern "C" void kernel_launch(void* const* d_in, const int* in_sizes, int n_in,
                              void* d_out, int out_size)
{
    const float* hidden = (const float*)d_in[1];
    const float* w_q    = (const float*)d_in[2];
    const float* w_kv_a = (const float*)d_in[3];
    const float* ln_w   = (const float*)d_in[4];
    const float* w_kv_b = (const float*)d_in[5];
    const float* w_o    = (const float*)d_in[6];
    float* out = (float*)d_out;

    float *q_p, *lat_p, *kva_p, *kpe_p, *kv_p, *attn_p;
    cudaGetSymbolAddress((void**)&q_p,    g_q);
    cudaGetSymbolAddress((void**)&lat_p,  g_latent);
    cudaGetSymbolAddress((void**)&kva_p,  g_kva);
    cudaGetSymbolAddress((void**)&kpe_p,  g_kpe);
    cudaGetSymbolAddress((void**)&kv_p,   g_kv);
    cudaGetSymbolAddress((void**)&attn_p, g_attn);

    cudaFuncSetAttribute(gemm_tf32,
                         cudaFuncAttributeMaxDynamicSharedMemorySize, GEMM_SMEM);
    cudaFuncSetAttribute(mla_attn_tc,
                         cudaFuncAttributeMaxDynamicSharedMemorySize, ATTN_SMEM);

    dim3 blk(256);
    gemm_tf32<<<dim3(QW / 128, TT / 128), blk, GEMM_SMEM>>>(hidden, w_q, q_p, TT, QW, HIDDEN);
    gemm_tf32<<<dim3((LATW + 127) / 128, TT / 128), blk, GEMM_SMEM>>>(hidden, w_kv_a, lat_p, TT, LATW, HIDDEN);
    rmsnorm_kernel<<<TT, 256>>>(lat_p, ln_w, kva_p);
    rope_k_kernel<<<(TT * (DR / 2) + 255) / 256, 256>>>(lat_p, kpe_p);
    gemm_tf32<<<dim3(KVW / 128, TT / 128), blk, GEMM_SMEM>>>(kva_p, w_kv_b, kv_p, TT, KVW, KV_LORA);
    rope_q_kernel<<<(TT * NH * (DR / 2) + 255) / 256, 256>>>(q_p);
    mla_attn_tc<<<dim3(TT / ABM, NH), blk, ATTN_SMEM>>>(q_p, kv_p, kpe_p, attn_p);
    gemm_tf32<<<dim3(HIDDEN / 128, TT / 128), blk, GEMM_SMEM>>>(attn_p, w_o, out, TT, HIDDEN, NH * DVV);
}

// round 6
// speedup vs baseline: 3.7146x; 1.0006x over previous
#include <cuda_runtime.h>
#include <cuda_bf16.h>
#include <cstdint>
#include <math.h>

#define TT 2048
#define HIDDEN 2048
#define NH 16
#define DN 128
#define DR 64
#define DVV 128
#define KV_LORA 512
#define DQ (DN + DR)          // 192
#define QW (NH * DQ)          // 3072
#define KVW (NH * (DN + DVV)) // 4096
#define LATW (KV_LORA + DR)   // 576

// ---------------- scratch ----------------------------------------------------
__device__ float g_q[TT * QW];
__device__ float g_latent[TT * LATW];
__device__ float g_kva[TT * KV_LORA];
__device__ float g_kpe[TT * DR];
__device__ float g_kv[TT * KVW];
__device__ float g_attn[TT * NH * DVV];

// ---------------- helpers -----------------------------------------------------
__device__ __forceinline__ uint32_t f2tf32(float x) {
    uint32_t r;
    asm("cvt.rna.tf32.f32 %0, %1;" : "=r"(r) : "f"(x));
    return r;
}

__device__ __forceinline__ void mma_tf32(float c[4], const uint32_t a[4], const uint32_t b[2]) {
    asm volatile(
        "mma.sync.aligned.m16n8k8.row.col.f32.tf32.tf32.f32 "
        "{%0,%1,%2,%3}, {%4,%5,%6,%7}, {%8,%9}, {%0,%1,%2,%3};"
        : "+f"(c[0]), "+f"(c[1]), "+f"(c[2]), "+f"(c[3])
        : "r"(a[0]), "r"(a[1]), "r"(a[2]), "r"(a[3]), "r"(b[0]), "r"(b[1]));
}

__device__ __forceinline__ uint32_t smem_u32(const void* p) {
    return (uint32_t)__cvta_generic_to_shared(p);
}

__device__ __forceinline__ void cp16(uint32_t dst, const void* src, int src_bytes) {
    asm volatile("cp.async.cg.shared.global [%0], [%1], 16, %2;"
                 :: "r"(dst), "l"(src), "r"(src_bytes));
}
#define CP_COMMIT() asm volatile("cp.async.commit_group;")
#define CP_WAIT(n)  asm volatile("cp.async.wait_group %0;" :: "n"(n))

// ---------------- TF32 GEMM: 128x256 tile, 8 warps x (64x64), 3-stage cp.async -
#define GSTAGES 3
#define GA_STRIDE 36
#define GB_STRIDE 264
#define GAW (128 * GA_STRIDE)            // 4608 words
#define GBW (32 * GB_STRIDE)             // 8448 words
#define GSTAGE_W (GAW + GBW)             // 13056 words
#define GEMM_SMEM (GSTAGES * GSTAGE_W * 4)  // 156672 B

__global__ __launch_bounds__(256, 1) void gemm_tf32(
    const float* __restrict__ A, const float* __restrict__ B,
    float* __restrict__ C, int M, int N, int K)
{
    extern __shared__ float gsm[];
    const uint32_t smBase = smem_u32(gsm);

    const int tid  = threadIdx.x;
    const int lane = tid & 31, warp = tid >> 5;
    const int warpM = warp & 1;           // 64-row slab
    const int warpN = warp >> 1;          // 0..3 -> 64-col slab
    const int gid = lane >> 2, tig = lane & 3;
    const int m0 = blockIdx.y * 128;
    const int n0 = blockIdx.x * 256;

    // staging coords
    const int ar = tid >> 3, ac = (tid & 7) * 4;    // A: rows ar+32i (i<4), cols ac..ac+3
    const int br = tid >> 6, bc = (tid & 63) * 4;   // B: rows br+4i (i<8), cols bc..bc+3

    const int nslab = K >> 5;

    auto issue_slab = [&](int slab) {
        const int k0 = slab * 32;
        const uint32_t stg = smBase + (uint32_t)((slab % GSTAGES) * GSTAGE_W) * 4;
        #pragma unroll
        for (int i = 0; i < 4; i++) {
            uint32_t dst = stg + (uint32_t)((ar + 32 * i) * GA_STRIDE + ac) * 4;
            cp16(dst, &A[(size_t)(m0 + ar + 32 * i) * K + k0 + ac], 16);
        }
        const int col = n0 + bc;
        const int ok = (col < N) ? 16 : 0;
        #pragma unroll
        for (int i = 0; i < 8; i++) {
            uint32_t dst = stg + (uint32_t)(GAW + (br + 4 * i) * GB_STRIDE + bc) * 4;
            cp16(dst, &B[(size_t)(k0 + br + 4 * i) * N + col], ok);
        }
    };

    #pragma unroll
    for (int s = 0; s < GSTAGES - 1; s++) {
        if (s < nslab) issue_slab(s);
        CP_COMMIT();
    }

    float c[4][8][4] = {};

    for (int i = 0; i < nslab; i++) {
        CP_WAIT(GSTAGES - 2);
        __syncthreads();

        if (i + GSTAGES - 1 < nslab) issue_slab(i + GSTAGES - 1);
        CP_COMMIT();

        const float* Ab = gsm + (i % GSTAGES) * GSTAGE_W;
        const float* Bb = Ab + GAW;

        #pragma unroll
        for (int ks = 0; ks < 4; ks++) {
            const int kb = ks * 8;
            uint32_t a[4][4], b[8][2];
            #pragma unroll
            for (int mt = 0; mt < 4; mt++) {
                int r = warpM * 64 + mt * 16 + gid;
                a[mt][0] = f2tf32(Ab[r * GA_STRIDE + kb + tig]);
                a[mt][1] = f2tf32(Ab[(r + 8) * GA_STRIDE + kb + tig]);
                a[mt][2] = f2tf32(Ab[r * GA_STRIDE + kb + tig + 4]);
                a[mt][3] = f2tf32(Ab[(r + 8) * GA_STRIDE + kb + tig + 4]);
            }
            #pragma unroll
            for (int nt = 0; nt < 8; nt++) {
                int cc = warpN * 64 + nt * 8 + gid;
                b[nt][0] = f2tf32(Bb[(kb + tig) * GB_STRIDE + cc]);
                b[nt][1] = f2tf32(Bb[(kb + tig + 4) * GB_STRIDE + cc]);
            }
            #pragma unroll
            for (int mt = 0; mt < 4; mt++)
                #pragma unroll
                for (int nt = 0; nt < 8; nt++)
                    mma_tf32(c[mt][nt], a[mt], b[nt]);
        }
    }

    #pragma unroll
    for (int mt = 0; mt < 4; mt++) {
        #pragma unroll
        for (int nt = 0; nt < 8; nt++) {
            int r = m0 + warpM * 64 + mt * 16 + gid;
            int cc = n0 + warpN * 64 + nt * 8 + tig * 2;
            if (cc < N) {
                *reinterpret_cast<float2*>(&C[(size_t)r * N + cc]) =
                    make_float2(c[mt][nt][0], c[mt][nt][1]);
                *reinterpret_cast<float2*>(&C[(size_t)(r + 8) * N + cc]) =
                    make_float2(c[mt][nt][2], c[mt][nt][3]);
            }
        }
    }
}

// ---------------- rmsnorm -----------------------------------------------------
__global__ __launch_bounds__(256) void rmsnorm_kernel(
    const float* __restrict__ latent, const float* __restrict__ w,
    float* __restrict__ out)
{
    const int t = blockIdx.x;
    const float* x = latent + (size_t)t * LATW;
    __shared__ float red[8];
    float ss = 0.f;
    for (int i = threadIdx.x; i < KV_LORA; i += 256) { float v = x[i]; ss += v * v; }
    #pragma unroll
    for (int o = 16; o > 0; o >>= 1) ss += __shfl_xor_sync(~0u, ss, o);
    if ((threadIdx.x & 31) == 0) red[threadIdx.x >> 5] = ss;
    __syncthreads();
    if (threadIdx.x == 0) {
        float v = 0.f;
        #pragma unroll
        for (int i = 0; i < 8; i++) v += red[i];
        red[0] = v;
    }
    __syncthreads();
    const float inv = rsqrtf(red[0] / (float)KV_LORA + 1e-6f);
    for (int i = threadIdx.x; i < KV_LORA; i += 256)
        out[(size_t)t * KV_LORA + i] = x[i] * inv * w[i];
}

// ---------------- non-neox RoPE ------------------------------------------------
__device__ __forceinline__ void rope_pair(float p, int i, float& x1, float& x2) {
    float inv = 1.0f / powf(10000.0f, (float)(2 * i) / (float)DR);
    float f = p * inv;
    float c = cosf(f), s = sinf(f);
    float o1 = x1 * c - x2 * s;
    float o2 = x2 * c + x1 * s;
    x1 = o1; x2 = o2;
}

__global__ __launch_bounds__(256) void rope_k_kernel(
    const float* __restrict__ latent, float* __restrict__ kpe)
{
    int idx = blockIdx.x * blockDim.x + threadIdx.x;
    if (idx >= TT * (DR / 2)) return;
    int t = idx / (DR / 2), i = idx % (DR / 2);
    float x1 = latent[(size_t)t * LATW + KV_LORA + 2 * i];
    float x2 = latent[(size_t)t * LATW + KV_LORA + 2 * i + 1];
    rope_pair((float)t, i, x1, x2);
    kpe[(size_t)t * DR + 2 * i]     = x1;
    kpe[(size_t)t * DR + 2 * i + 1] = x2;
}

__global__ __launch_bounds__(256) void rope_q_kernel(float* __restrict__ q)
{
    int idx = blockIdx.x * blockDim.x + threadIdx.x;
    if (idx >= TT * NH * (DR / 2)) return;
    int i = idx & 31;
    int h = (idx >> 5) & (NH - 1);
    int t = idx >> 9;
    float* base = q + (size_t)t * QW + h * DQ + DN;
    float x1 = base[2 * i], x2 = base[2 * i + 1];
    rope_pair((float)t, i, x1, x2);
    base[2 * i] = x1; base[2 * i + 1] = x2;
}

// ---------------- tensor-core flash attention with cp.async overlap ------------
#define ABM 128
#define ABN 64
#define DQP (DQ + 4)    // 196
#define DVP (DVV + 4)   // 132
#define BNP (ABN + 4)   // 68
#define SQ_W (ABM * DQP)
#define SK_W (ABN * DQP)
#define SV_W (ABN * DVP)
#define SP_W (ABM * BNP)
#define ATTN_SMEM ((SQ_W + SK_W + SV_W + SP_W) * 4)  // 219136 B

__global__ __launch_bounds__(256) void mla_attn_tc(
    const float* __restrict__ q, const float* __restrict__ kv,
    const float* __restrict__ kpe, float* __restrict__ out)
{
    extern __shared__ uint32_t asm_[];
    uint32_t* sQ  = asm_;
    float*    sKf = (float*)(asm_ + SQ_W);
    float*    sVf = (float*)(asm_ + SQ_W + SK_W);
    uint32_t* sP  = asm_ + SQ_W + SK_W + SV_W;
    uint32_t* sKu = (uint32_t*)sKf;
    uint32_t* sVu = (uint32_t*)sVf;
    const uint32_t sKb = smem_u32(sKf);
    const uint32_t sVb = smem_u32(sVf);

    const int h  = blockIdx.y;
    // heavy tiles (large bx) first: launch order is ascending blockIdx.x
    const int bx = (int)gridDim.x - 1 - (int)blockIdx.x;
    const int q0 = bx * ABM;
    const int tid = threadIdx.x;
    const int lane = tid & 31, warp = tid >> 5;
    const int gid = lane >> 2, tig = lane & 3;
    const int r0 = warp * 16;
    const float scale = rsqrtf((float)DQ);

    auto issueK = [&](int k0) {
        #pragma unroll
        for (int j = 0; j < 12; j++) {
            int c = j * 256 + tid;
            int r = c / 48, col4 = (c % 48) * 4;
            uint32_t dst = sKb + (uint32_t)(r * DQP + col4) * 4;
            const float* src = (col4 < DN)
                ? &kv[(size_t)(k0 + r) * KVW + h * (DN + DVV) + col4]
                : &kpe[(size_t)(k0 + r) * DR + (col4 - DN)];
            cp16(dst, src, 16);
        }
    };
    auto issueV = [&](int k0) {
        #pragma unroll
        for (int j = 0; j < 8; j++) {
            int c = j * 256 + tid;
            int r = c / 32, col4 = (c % 32) * 4;
            uint32_t dst = sVb + (uint32_t)(r * DVP + col4) * 4;
            cp16(dst, &kv[(size_t)(k0 + r) * KVW + h * (DN + DVV) + DN + col4], 16);
        }
    };

    issueK(0);
    CP_COMMIT();

    for (int idx = tid; idx < ABM * DQ; idx += 256) {
        int r = idx / DQ, d = idx % DQ;
        sQ[r * DQP + d] = f2tf32(q[(size_t)(q0 + r) * QW + h * DQ + d] * scale);
    }

    float o[16][4] = {};
    float m_a = -1e30f, m_b = -1e30f, l_a = 0.f, l_b = 0.f;
    const int jt_end = 2 * bx + 1;

    for (int jt = 0; jt <= jt_end; jt++) {
        const int k0 = jt * ABN;

        CP_WAIT(0);
        __syncthreads();

        issueV(k0);
        CP_COMMIT();

        #pragma unroll
        for (int j = 0; j < 12; j++) {
            int c = j * 256 + tid;
            int r = c / 48, col4 = (c % 48) * 4;
            float4 v = *reinterpret_cast<const float4*>(&sKf[r * DQP + col4]);
            uint32_t* p = &sKu[r * DQP + col4];
            p[0] = f2tf32(v.x); p[1] = f2tf32(v.y);
            p[2] = f2tf32(v.z); p[3] = f2tf32(v.w);
        }
        __syncthreads();

        float s[8][4] = {};
        #pragma unroll 6
        for (int kb = 0; kb < DQ; kb += 8) {
            uint32_t a[4];
            a[0] = sQ[(r0 + gid) * DQP + kb + tig];
            a[1] = sQ[(r0 + gid + 8) * DQP + kb + tig];
            a[2] = sQ[(r0 + gid) * DQP + kb + tig + 4];
            a[3] = sQ[(r0 + gid + 8) * DQP + kb + tig + 4];
            #pragma unroll
            for (int nt = 0; nt < 8; nt++) {
                uint32_t b[2];
                b[0] = sKu[(nt * 8 + gid) * DQP + kb + tig];
                b[1] = sKu[(nt * 8 + gid) * DQP + kb + tig + 4];
                mma_tf32(s[nt], a, b);
            }
        }
        __syncthreads();

        if (jt < jt_end) {
            issueK(k0 + ABN);
            CP_COMMIT();
        }

        if (jt >= 2 * bx) {
            const int rowA = q0 + r0 + gid;
            const int rowB = rowA + 8;
            #pragma unroll
            for (int nt = 0; nt < 8; nt++) {
                int c0 = k0 + nt * 8 + tig * 2;
                if (c0 > rowA)     s[nt][0] = -1e30f;
                if (c0 + 1 > rowA) s[nt][1] = -1e30f;
                if (c0 > rowB)     s[nt][2] = -1e30f;
                if (c0 + 1 > rowB) s[nt][3] = -1e30f;
            }
        }

        float mxa = -1e30f, mxb = -1e30f;
        #pragma unroll
        for (int nt = 0; nt < 8; nt++) {
            mxa = fmaxf(mxa, fmaxf(s[nt][0], s[nt][1]));
            mxb = fmaxf(mxb, fmaxf(s[nt][2], s[nt][3]));
        }
        mxa = fmaxf(mxa, __shfl_xor_sync(~0u, mxa, 1));
        mxa = fmaxf(mxa, __shfl_xor_sync(~0u, mxa, 2));
        mxb = fmaxf(mxb, __shfl_xor_sync(~0u, mxb, 1));
        mxb = fmaxf(mxb, __shfl_xor_sync(~0u, mxb, 2));

        float mna = fmaxf(m_a, mxa), mnb = fmaxf(m_b, mxb);
        float alpha_a = __expf(m_a - mna), alpha_b = __expf(m_b - mnb);
        float sa = 0.f, sb = 0.f;
        #pragma unroll
        for (int nt = 0; nt < 8; nt++) {
            s[nt][0] = __expf(s[nt][0] - mna);
            s[nt][1] = __expf(s[nt][1] - mna);
            s[nt][2] = __expf(s[nt][2] - mnb);
            s[nt][3] = __expf(s[nt][3] - mnb);
            sa += s[nt][0] + s[nt][1];
            sb += s[nt][2] + s[nt][3];
        }
        sa += __shfl_xor_sync(~0u, sa, 1); sa += __shfl_xor_sync(~0u, sa, 2);
        sb += __shfl_xor_sync(~0u, sb, 1); sb += __shfl_xor_sync(~0u, sb, 2);
        l_a = l_a * alpha_a + sa;
        l_b = l_b * alpha_b + sb;
        m_a = mna; m_b = mnb;

        #pragma unroll
        for (int nt = 0; nt < 16; nt++) {
            o[nt][0] *= alpha_a; o[nt][1] *= alpha_a;
            o[nt][2] *= alpha_b; o[nt][3] *= alpha_b;
        }

        if (jt < jt_end) { CP_WAIT(1); } else { CP_WAIT(0); }
        __syncthreads();

        #pragma unroll
        for (int j = 0; j < 8; j++) {
            int c = j * 256 + tid;
            int r = c / 32, col4 = (c % 32) * 4;
            float4 v = *reinterpret_cast<const float4*>(&sVf[r * DVP + col4]);
            uint32_t* p = &sVu[r * DVP + col4];
            p[0] = f2tf32(v.x); p[1] = f2tf32(v.y);
            p[2] = f2tf32(v.z); p[3] = f2tf32(v.w);
        }

        #pragma unroll
        for (int nt = 0; nt < 8; nt++) {
            sP[(r0 + gid) * BNP + nt * 8 + tig * 2]         = f2tf32(s[nt][0]);
            sP[(r0 + gid) * BNP + nt * 8 + tig * 2 + 1]     = f2tf32(s[nt][1]);
            sP[(r0 + gid + 8) * BNP + nt * 8 + tig * 2]     = f2tf32(s[nt][2]);
            sP[(r0 + gid + 8) * BNP + nt * 8 + tig * 2 + 1] = f2tf32(s[nt][3]);
        }
        __syncthreads();

        #pragma unroll
        for (int kb = 0; kb < ABN; kb += 8) {
            uint32_t a[4];
            a[0] = sP[(r0 + gid) * BNP + kb + tig];
            a[1] = sP[(r0 + gid + 8) * BNP + kb + tig];
            a[2] = sP[(r0 + gid) * BNP + kb + tig + 4];
            a[3] = sP[(r0 + gid + 8) * BNP + kb + tig + 4];
            #pragma unroll
            for (int nt = 0; nt < 16; nt++) {
                uint32_t b[2];
                b[0] = sVu[(kb + tig) * DVP + nt * 8 + gid];
                b[1] = sVu[(kb + tig + 4) * DVP + nt * 8 + gid];
                mma_tf32(o[nt], a, b);
            }
        }
    }

    const float inv_a = 1.0f / l_a, inv_b = 1.0f / l_b;
    const int rowA = q0 + r0 + gid, rowB = rowA + 8;
    #pragma unroll
    for (int nt = 0; nt < 16; nt++) {
        int cc = h * DVV + nt * 8 + tig * 2;
        *reinterpret_cast<float2*>(&out[(size_t)rowA * (NH * DVV) + cc]) =
            make_float2(o[nt][0] * inv_a, o[nt][1] * inv_a);
        *reinterpret_cast<float2*>(&out[(size_t)rowB * (NH * DVV) + cc]) =
            make_float2(o[nt][2] * inv_b, o[nt][3] * inv_b);
    }
}

// ---------------- launch --------------------------------------------------------
extern "C" void kernel_launch(void* const* d_in, const int* in_sizes, int n_in,
                              void* d_out, int out_size)
{
    const float* hidden = (const float*)d_in[1];
    const float* w_q    = (const float*)d_in[2];
    const float* w_kv_a = (const float*)d_in[3];
    const float* ln_w   = (const float*)d_in[4];
    const float* w_kv_b = (const float*)d_in[5];
    const float* w_o    = (const float*)d_in[6];
    float* out = (float*)d_out;

    float *q_p, *lat_p, *kva_p, *kpe_p, *kv_p, *attn_p;
    cudaGetSymbolAddress((void**)&q_p,    g_q);
    cudaGetSymbolAddress((void**)&lat_p,  g_latent);
    cudaGetSymbolAddress((void**)&kva_p,  g_kva);
    cudaGetSymbolAddress((void**)&kpe_p,  g_kpe);
    cudaGetSymbolAddress((void**)&kv_p,   g_kv);
    cudaGetSymbolAddress((void**)&attn_p, g_attn);

    cudaFuncSetAttribute(gemm_tf32,
                         cudaFuncAttributeMaxDynamicSharedMemorySize, GEMM_SMEM);
    cudaFuncSetAttribute(mla_attn_tc,
                         cudaFuncAttributeMaxDynamicSharedMemorySize, ATTN_SMEM);

    dim3 blk(256);
    // q = hidden @ w_q  [2048 x 3072]
    gemm_tf32<<<dim3(QW / 256, TT / 128), blk, GEMM_SMEM>>>(hidden, w_q, q_p, TT, QW, HIDDEN);
    // latent = hidden @ w_kv_a  [2048 x 576] (3 partial N-tiles)
    gemm_tf32<<<dim3((LATW + 255) / 256, TT / 128), blk, GEMM_SMEM>>>(hidden, w_kv_a, lat_p, TT, LATW, HIDDEN);
    rmsnorm_kernel<<<TT, 256>>>(lat_p, ln_w, kva_p);
    rope_k_kernel<<<(TT * (DR / 2) + 255) / 256, 256>>>(lat_p, kpe_p);
    // kv = kv_a @ w_kv_b  [2048 x 4096]
    gemm_tf32<<<dim3(KVW / 256, TT / 128), blk, GEMM_SMEM>>>(kva_p, w_kv_b, kv_p, TT, KVW, KV_LORA);
    rope_q_kernel<<<(TT * NH * (DR / 2) + 255) / 256, 256>>>(q_p);
    mla_attn_tc<<<dim3(TT / ABM, NH), blk, ATTN_SMEM>>>(q_p, kv_p, kpe_p, attn_p);
    // out = attn @ w_o  [2048 x 2048]
    gemm_tf32<<<dim3(HIDDEN / 256, TT / 128), blk, GEMM_SMEM>>>(attn_p, w_o, out, TT, HIDDEN, NH * DVV);
}

// round 7
// speedup vs baseline: 5.1028x; 1.3737x over previous
#include <cuda_runtime.h>
#include <cuda_bf16.h>
#include <cstdint>
#include <math.h>

#define TT 2048
#define HIDDEN 2048
#define NH 16
#define DN 128
#define DR 64
#define DVV 128
#define KV_LORA 512
#define DQ (DN + DR)          // 192
#define QW (NH * DQ)          // 3072
#define KVW (NH * (DN + DVV)) // 4096
#define LATW (KV_LORA + DR)   // 576

// ---------------- scratch ----------------------------------------------------
__device__ float g_q[TT * QW];
__device__ float g_latent[TT * LATW];
__device__ float g_kva[TT * KV_LORA];
__device__ float g_kpe[TT * DR];
__device__ float g_kv[TT * KVW];
__device__ float g_attn[TT * NH * DVV];

// ---------------- helpers -----------------------------------------------------
__device__ __forceinline__ uint32_t f2tf32(float x) {
    uint32_t r;
    asm("cvt.rna.tf32.f32 %0, %1;" : "=r"(r) : "f"(x));
    return r;
}

__device__ __forceinline__ void mma_tf32(float c[4], const uint32_t a[4], const uint32_t b[2]) {
    asm volatile(
        "mma.sync.aligned.m16n8k8.row.col.f32.tf32.tf32.f32 "
        "{%0,%1,%2,%3}, {%4,%5,%6,%7}, {%8,%9}, {%0,%1,%2,%3};"
        : "+f"(c[0]), "+f"(c[1]), "+f"(c[2]), "+f"(c[3])
        : "r"(a[0]), "r"(a[1]), "r"(a[2]), "r"(a[3]), "r"(b[0]), "r"(b[1]));
}

__device__ __forceinline__ uint32_t smem_u32(const void* p) {
    return (uint32_t)__cvta_generic_to_shared(p);
}

__device__ __forceinline__ void cp16(uint32_t dst, const void* src, int src_bytes) {
    asm volatile("cp.async.cg.shared.global [%0], [%1], 16, %2;"
                 :: "r"(dst), "l"(src), "r"(src_bytes));
}
#define CP_COMMIT() asm volatile("cp.async.commit_group;")
#define CP_WAIT(n)  asm volatile("cp.async.wait_group %0;" :: "n"(n))

__device__ __forceinline__ void rope_pair(float p, int i, float& x1, float& x2) {
    float inv = 1.0f / powf(10000.0f, (float)(2 * i) / (float)DR);
    float f = p * inv;
    float c = cosf(f), s = sinf(f);
    float o1 = x1 * c - x2 * s;
    float o2 = x2 * c + x1 * s;
    x1 = o1; x2 = o2;
}

// ---------------- TF32 GEMM: 128x256 tile, dual-output, 4-stage cp.async -------
// Computes C1[M,N1] = A@B1 and C2[M,N2] = A@B2 in one grid (N-tiles concatenated).
#define GSTAGES 4
#define GA_STRIDE 36
#define GB_STRIDE 264
#define GAW (128 * GA_STRIDE)            // 4608 words
#define GBW (32 * GB_STRIDE)             // 8448 words
#define GSTAGE_W (GAW + GBW)             // 13056 words
#define GEMM_SMEM (GSTAGES * GSTAGE_W * 4)  // 208896 B

__global__ __launch_bounds__(256, 1) void gemm_tf32_dual(
    const float* __restrict__ A,
    const float* __restrict__ B1, float* __restrict__ C1, int N1,
    const float* __restrict__ B2, float* __restrict__ C2, int N2,
    int K)
{
    extern __shared__ float gsm[];
    const uint32_t smBase = smem_u32(gsm);

    // select output per CTA column-tile
    const int tiles1 = (N1 + 255) / 256;
    const float* B; float* C; int N, n0;
    if ((int)blockIdx.x < tiles1) {
        B = B1; C = C1; N = N1; n0 = blockIdx.x * 256;
    } else {
        B = B2; C = C2; N = N2; n0 = (blockIdx.x - tiles1) * 256;
    }

    const int tid  = threadIdx.x;
    const int lane = tid & 31, warp = tid >> 5;
    const int warpM = warp & 1;
    const int warpN = warp >> 1;
    const int gid = lane >> 2, tig = lane & 3;
    const int m0 = blockIdx.y * 128;

    const int ar = tid >> 3, ac = (tid & 7) * 4;
    const int br = tid >> 6, bc = (tid & 63) * 4;

    const int nslab = K >> 5;

    auto issue_slab = [&](int slab) {
        const int k0 = slab * 32;
        const uint32_t stg = smBase + (uint32_t)((slab & (GSTAGES - 1)) * GSTAGE_W) * 4;
        #pragma unroll
        for (int i = 0; i < 4; i++) {
            uint32_t dst = stg + (uint32_t)((ar + 32 * i) * GA_STRIDE + ac) * 4;
            cp16(dst, &A[(size_t)(m0 + ar + 32 * i) * K + k0 + ac], 16);
        }
        const int col = n0 + bc;
        const int ok = (col < N) ? 16 : 0;
        #pragma unroll
        for (int i = 0; i < 8; i++) {
            uint32_t dst = stg + (uint32_t)(GAW + (br + 4 * i) * GB_STRIDE + bc) * 4;
            cp16(dst, &B[(size_t)(k0 + br + 4 * i) * N + col], ok);
        }
    };

    #pragma unroll
    for (int s = 0; s < GSTAGES - 1; s++) {
        if (s < nslab) issue_slab(s);
        CP_COMMIT();
    }

    float c[4][8][4] = {};

    for (int i = 0; i < nslab; i++) {
        CP_WAIT(GSTAGES - 2);
        __syncthreads();

        if (i + GSTAGES - 1 < nslab) issue_slab(i + GSTAGES - 1);
        CP_COMMIT();

        const float* Ab = gsm + (i & (GSTAGES - 1)) * GSTAGE_W;
        const float* Bb = Ab + GAW;

        #pragma unroll
        for (int ks = 0; ks < 4; ks++) {
            const int kb = ks * 8;
            uint32_t a[4][4], b[8][2];
            #pragma unroll
            for (int mt = 0; mt < 4; mt++) {
                int r = warpM * 64 + mt * 16 + gid;
                a[mt][0] = f2tf32(Ab[r * GA_STRIDE + kb + tig]);
                a[mt][1] = f2tf32(Ab[(r + 8) * GA_STRIDE + kb + tig]);
                a[mt][2] = f2tf32(Ab[r * GA_STRIDE + kb + tig + 4]);
                a[mt][3] = f2tf32(Ab[(r + 8) * GA_STRIDE + kb + tig + 4]);
            }
            #pragma unroll
            for (int nt = 0; nt < 8; nt++) {
                int cc = warpN * 64 + nt * 8 + gid;
                b[nt][0] = f2tf32(Bb[(kb + tig) * GB_STRIDE + cc]);
                b[nt][1] = f2tf32(Bb[(kb + tig + 4) * GB_STRIDE + cc]);
            }
            #pragma unroll
            for (int mt = 0; mt < 4; mt++)
                #pragma unroll
                for (int nt = 0; nt < 8; nt++)
                    mma_tf32(c[mt][nt], a[mt], b[nt]);
        }
    }

    #pragma unroll
    for (int mt = 0; mt < 4; mt++) {
        #pragma unroll
        for (int nt = 0; nt < 8; nt++) {
            int r = m0 + warpM * 64 + mt * 16 + gid;
            int cc = n0 + warpN * 64 + nt * 8 + tig * 2;
            if (cc < N) {
                *reinterpret_cast<float2*>(&C[(size_t)r * N + cc]) =
                    make_float2(c[mt][nt][0], c[mt][nt][1]);
                *reinterpret_cast<float2*>(&C[(size_t)(r + 8) * N + cc]) =
                    make_float2(c[mt][nt][2], c[mt][nt][3]);
            }
        }
    }
}

// ---------------- rmsnorm + rope_k fused ---------------------------------------
__global__ __launch_bounds__(256) void rmsnorm_ropek_kernel(
    const float* __restrict__ latent, const float* __restrict__ w,
    float* __restrict__ out, float* __restrict__ kpe)
{
    const int t = blockIdx.x;
    const float* x = latent + (size_t)t * LATW;
    __shared__ float red[8];
    float ss = 0.f;
    for (int i = threadIdx.x; i < KV_LORA; i += 256) { float v = x[i]; ss += v * v; }
    #pragma unroll
    for (int o = 16; o > 0; o >>= 1) ss += __shfl_xor_sync(~0u, ss, o);
    if ((threadIdx.x & 31) == 0) red[threadIdx.x >> 5] = ss;
    __syncthreads();
    if (threadIdx.x == 0) {
        float v = 0.f;
        #pragma unroll
        for (int i = 0; i < 8; i++) v += red[i];
        red[0] = v;
    }
    __syncthreads();
    const float inv = rsqrtf(red[0] / (float)KV_LORA + 1e-6f);
    for (int i = threadIdx.x; i < KV_LORA; i += 256)
        out[(size_t)t * KV_LORA + i] = x[i] * inv * w[i];

    // rope k_pe (independent of rmsnorm result)
    if (threadIdx.x < DR / 2) {
        int i = threadIdx.x;
        float x1 = x[KV_LORA + 2 * i], x2 = x[KV_LORA + 2 * i + 1];
        rope_pair((float)t, i, x1, x2);
        kpe[(size_t)t * DR + 2 * i]     = x1;
        kpe[(size_t)t * DR + 2 * i + 1] = x2;
    }
}

// ---------------- tensor-core flash attention (LPT order, fused rope_q) --------
#define ABM 128
#define ABN 64
#define DQP (DQ + 4)    // 196
#define DVP (DVV + 4)   // 132
#define BNP (ABN + 4)   // 68
#define SQ_W (ABM * DQP)
#define SK_W (ABN * DQP)
#define SV_W (ABN * DVP)
#define SP_W (ABM * BNP)
#define ATTN_SMEM ((SQ_W + SK_W + SV_W + SP_W) * 4)  // 219136 B

__global__ __launch_bounds__(256) void mla_attn_tc(
    const float* __restrict__ q, const float* __restrict__ kv,
    const float* __restrict__ kpe, float* __restrict__ out)
{
    extern __shared__ uint32_t asm_[];
    uint32_t* sQ  = asm_;
    float*    sKf = (float*)(asm_ + SQ_W);
    float*    sVf = (float*)(asm_ + SQ_W + SK_W);
    uint32_t* sP  = asm_ + SQ_W + SK_W + SV_W;
    uint32_t* sKu = (uint32_t*)sKf;
    uint32_t* sVu = (uint32_t*)sVf;
    const uint32_t sKb = smem_u32(sKf);
    const uint32_t sVb = smem_u32(sVf);

    // LPT: heaviest q-tiles (largest bx) scheduled first, across ALL heads
    const int bx = (TT / ABM - 1) - ((int)blockIdx.x >> 4);
    const int h  = (int)blockIdx.x & (NH - 1);
    const int q0 = bx * ABM;
    const int tid = threadIdx.x;
    const int lane = tid & 31, warp = tid >> 5;
    const int gid = lane >> 2, tig = lane & 3;
    const int r0 = warp * 16;
    const float scale = rsqrtf((float)DQ);

    auto issueK = [&](int k0) {
        #pragma unroll
        for (int j = 0; j < 12; j++) {
            int c = j * 256 + tid;
            int r = c / 48, col4 = (c % 48) * 4;
            uint32_t dst = sKb + (uint32_t)(r * DQP + col4) * 4;
            const float* src = (col4 < DN)
                ? &kv[(size_t)(k0 + r) * KVW + h * (DN + DVV) + col4]
                : &kpe[(size_t)(k0 + r) * DR + (col4 - DN)];
            cp16(dst, src, 16);
        }
    };
    auto issueV = [&](int k0) {
        #pragma unroll
        for (int j = 0; j < 8; j++) {
            int c = j * 256 + tid;
            int r = c / 32, col4 = (c % 32) * 4;
            uint32_t dst = sVb + (uint32_t)(r * DVP + col4) * 4;
            cp16(dst, &kv[(size_t)(k0 + r) * KVW + h * (DN + DVV) + DN + col4], 16);
        }
    };

    issueK(0);
    CP_COMMIT();

    // Q nope part
    for (int idx = tid; idx < ABM * DN; idx += 256) {
        int r = idx / DN, d = idx % DN;
        sQ[r * DQP + d] = f2tf32(q[(size_t)(q0 + r) * QW + h * DQ + d] * scale);
    }
    // Q pe part with fused rope
    for (int idx = tid; idx < ABM * (DR / 2); idx += 256) {
        int r = idx / (DR / 2), i = idx % (DR / 2);
        const float* bq = &q[(size_t)(q0 + r) * QW + h * DQ + DN];
        float x1 = bq[2 * i], x2 = bq[2 * i + 1];
        rope_pair((float)(q0 + r), i, x1, x2);
        sQ[r * DQP + DN + 2 * i]     = f2tf32(x1 * scale);
        sQ[r * DQP + DN + 2 * i + 1] = f2tf32(x2 * scale);
    }

    float o[16][4] = {};
    float m_a = -1e30f, m_b = -1e30f, l_a = 0.f, l_b = 0.f;
    const int jt_end = 2 * bx + 1;

    for (int jt = 0; jt <= jt_end; jt++) {
        const int k0 = jt * ABN;

        CP_WAIT(0);
        __syncthreads();

        issueV(k0);
        CP_COMMIT();

        #pragma unroll
        for (int j = 0; j < 12; j++) {
            int c = j * 256 + tid;
            int r = c / 48, col4 = (c % 48) * 4;
            float4 v = *reinterpret_cast<const float4*>(&sKf[r * DQP + col4]);
            uint32_t* p = &sKu[r * DQP + col4];
            p[0] = f2tf32(v.x); p[1] = f2tf32(v.y);
            p[2] = f2tf32(v.z); p[3] = f2tf32(v.w);
        }
        __syncthreads();

        float s[8][4] = {};
        #pragma unroll 6
        for (int kb = 0; kb < DQ; kb += 8) {
            uint32_t a[4];
            a[0] = sQ[(r0 + gid) * DQP + kb + tig];
            a[1] = sQ[(r0 + gid + 8) * DQP + kb + tig];
            a[2] = sQ[(r0 + gid) * DQP + kb + tig + 4];
            a[3] = sQ[(r0 + gid + 8) * DQP + kb + tig + 4];
            #pragma unroll
            for (int nt = 0; nt < 8; nt++) {
                uint32_t b[2];
                b[0] = sKu[(nt * 8 + gid) * DQP + kb + tig];
                b[1] = sKu[(nt * 8 + gid) * DQP + kb + tig + 4];
                mma_tf32(s[nt], a, b);
            }
        }
        __syncthreads();

        if (jt < jt_end) {
            issueK(k0 + ABN);
            CP_COMMIT();
        }

        if (jt >= 2 * bx) {
            const int rowA = q0 + r0 + gid;
            const int rowB = rowA + 8;
            #pragma unroll
            for (int nt = 0; nt < 8; nt++) {
                int c0 = k0 + nt * 8 + tig * 2;
                if (c0 > rowA)     s[nt][0] = -1e30f;
                if (c0 + 1 > rowA) s[nt][1] = -1e30f;
                if (c0 > rowB)     s[nt][2] = -1e30f;
                if (c0 + 1 > rowB) s[nt][3] = -1e30f;
            }
        }

        float mxa = -1e30f, mxb = -1e30f;
        #pragma unroll
        for (int nt = 0; nt < 8; nt++) {
            mxa = fmaxf(mxa, fmaxf(s[nt][0], s[nt][1]));
            mxb = fmaxf(mxb, fmaxf(s[nt][2], s[nt][3]));
        }
        mxa = fmaxf(mxa, __shfl_xor_sync(~0u, mxa, 1));
        mxa = fmaxf(mxa, __shfl_xor_sync(~0u, mxa, 2));
        mxb = fmaxf(mxb, __shfl_xor_sync(~0u, mxb, 1));
        mxb = fmaxf(mxb, __shfl_xor_sync(~0u, mxb, 2));

        float mna = fmaxf(m_a, mxa), mnb = fmaxf(m_b, mxb);
        float alpha_a = __expf(m_a - mna), alpha_b = __expf(m_b - mnb);
        float sa = 0.f, sb = 0.f;
        #pragma unroll
        for (int nt = 0; nt < 8; nt++) {
            s[nt][0] = __expf(s[nt][0] - mna);
            s[nt][1] = __expf(s[nt][1] - mna);
            s[nt][2] = __expf(s[nt][2] - mnb);
            s[nt][3] = __expf(s[nt][3] - mnb);
            sa += s[nt][0] + s[nt][1];
            sb += s[nt][2] + s[nt][3];
        }
        sa += __shfl_xor_sync(~0u, sa, 1); sa += __shfl_xor_sync(~0u, sa, 2);
        sb += __shfl_xor_sync(~0u, sb, 1); sb += __shfl_xor_sync(~0u, sb, 2);
        l_a = l_a * alpha_a + sa;
        l_b = l_b * alpha_b + sb;
        m_a = mna; m_b = mnb;

        #pragma unroll
        for (int nt = 0; nt < 16; nt++) {
            o[nt][0] *= alpha_a; o[nt][1] *= alpha_a;
            o[nt][2] *= alpha_b; o[nt][3] *= alpha_b;
        }

        if (jt < jt_end) { CP_WAIT(1); } else { CP_WAIT(0); }
        __syncthreads();

        #pragma unroll
        for (int j = 0; j < 8; j++) {
            int c = j * 256 + tid;
            int r = c / 32, col4 = (c % 32) * 4;
            float4 v = *reinterpret_cast<const float4*>(&sVf[r * DVP + col4]);
            uint32_t* p = &sVu[r * DVP + col4];
            p[0] = f2tf32(v.x); p[1] = f2tf32(v.y);
            p[2] = f2tf32(v.z); p[3] = f2tf32(v.w);
        }

        #pragma unroll
        for (int nt = 0; nt < 8; nt++) {
            sP[(r0 + gid) * BNP + nt * 8 + tig * 2]         = f2tf32(s[nt][0]);
            sP[(r0 + gid) * BNP + nt * 8 + tig * 2 + 1]     = f2tf32(s[nt][1]);
            sP[(r0 + gid + 8) * BNP + nt * 8 + tig * 2]     = f2tf32(s[nt][2]);
            sP[(r0 + gid + 8) * BNP + nt * 8 + tig * 2 + 1] = f2tf32(s[nt][3]);
        }
        __syncthreads();

        #pragma unroll
        for (int kb = 0; kb < ABN; kb += 8) {
            uint32_t a[4];
            a[0] = sP[(r0 + gid) * BNP + kb + tig];
            a[1] = sP[(r0 + gid + 8) * BNP + kb + tig];
            a[2] = sP[(r0 + gid) * BNP + kb + tig + 4];
            a[3] = sP[(r0 + gid + 8) * BNP + kb + tig + 4];
            #pragma unroll
            for (int nt = 0; nt < 16; nt++) {
                uint32_t b[2];
                b[0] = sVu[(kb + tig) * DVP + nt * 8 + gid];
                b[1] = sVu[(kb + tig + 4) * DVP + nt * 8 + gid];
                mma_tf32(o[nt], a, b);
            }
        }
    }

    const float inv_a = 1.0f / l_a, inv_b = 1.0f / l_b;
    const int rowA = q0 + r0 + gid, rowB = rowA + 8;
    #pragma unroll
    for (int nt = 0; nt < 16; nt++) {
        int cc = h * DVV + nt * 8 + tig * 2;
        *reinterpret_cast<float2*>(&out[(size_t)rowA * (NH * DVV) + cc]) =
            make_float2(o[nt][0] * inv_a, o[nt][1] * inv_a);
        *reinterpret_cast<float2*>(&out[(size_t)rowB * (NH * DVV) + cc]) =
            make_float2(o[nt][2] * inv_b, o[nt][3] * inv_b);
    }
}

// ---------------- launch --------------------------------------------------------
extern "C" void kernel_launch(void* const* d_in, const int* in_sizes, int n_in,
                              void* d_out, int out_size)
{
    const float* hidden = (const float*)d_in[1];
    const float* w_q    = (const float*)d_in[2];
    const float* w_kv_a = (const float*)d_in[3];
    const float* ln_w   = (const float*)d_in[4];
    const float* w_kv_b = (const float*)d_in[5];
    const float* w_o    = (const float*)d_in[6];
    float* out = (float*)d_out;

    float *q_p, *lat_p, *kva_p, *kpe_p, *kv_p, *attn_p;
    cudaGetSymbolAddress((void**)&q_p,    g_q);
    cudaGetSymbolAddress((void**)&lat_p,  g_latent);
    cudaGetSymbolAddress((void**)&kva_p,  g_kva);
    cudaGetSymbolAddress((void**)&kpe_p,  g_kpe);
    cudaGetSymbolAddress((void**)&kv_p,   g_kv);
    cudaGetSymbolAddress((void**)&attn_p, g_attn);

    cudaFuncSetAttribute(gemm_tf32_dual,
                         cudaFuncAttributeMaxDynamicSharedMemorySize, GEMM_SMEM);
    cudaFuncSetAttribute(mla_attn_tc,
                         cudaFuncAttributeMaxDynamicSharedMemorySize, ATTN_SMEM);

    dim3 blk(256);
    const int t1 = QW / 256;                 // 12
    const int t2 = (LATW + 255) / 256;       // 3

    // fused: q = hidden@w_q AND latent = hidden@w_kv_a  (one grid, 240 CTAs)
    gemm_tf32_dual<<<dim3(t1 + t2, TT / 128), blk, GEMM_SMEM>>>(
        hidden, w_q, q_p, QW, w_kv_a, lat_p, LATW, HIDDEN);
    // rmsnorm + rope_k fused
    rmsnorm_ropek_kernel<<<TT, 256>>>(lat_p, ln_w, kva_p, kpe_p);
    // kv = kv_a @ w_kv_b  [2048 x 4096]
    gemm_tf32_dual<<<dim3(KVW / 256, TT / 128), blk, GEMM_SMEM>>>(
        kva_p, w_kv_b, kv_p, KVW, (const float*)nullptr, (float*)nullptr, 0, KV_LORA);
    // attention (LPT-ordered flat grid; rope_q fused into Q staging)
    mla_attn_tc<<<(TT / ABM) * NH, blk, ATTN_SMEM>>>(q_p, kv_p, kpe_p, attn_p);
    // out = attn @ w_o  [2048 x 2048]
    gemm_tf32_dual<<<dim3(HIDDEN / 256, TT / 128), blk, GEMM_SMEM>>>(
        attn_p, w_o, out, HIDDEN, (const float*)nullptr, (float*)nullptr, 0, NH * DVV);
}

// round 8
// speedup vs baseline: 5.6017x; 1.0978x over previous
#include <cuda_runtime.h>
#include <cuda_bf16.h>
#include <cstdint>
#include <math.h>

#define TT 2048
#define HIDDEN 2048
#define NH 16
#define DN 128
#define DR 64
#define DVV 128
#define KV_LORA 512
#define DQ (DN + DR)          // 192
#define QW (NH * DQ)          // 3072
#define KVW (NH * (DN + DVV)) // 4096
#define LATW (KV_LORA + DR)   // 576

// ---------------- scratch ----------------------------------------------------
__device__ float g_q[TT * QW];
__device__ float g_latent[TT * LATW];
__device__ float g_kva[TT * KV_LORA];
__device__ float g_kpe[TT * DR];
__device__ float g_kv[TT * KVW];
__device__ float g_attn[TT * NH * DVV];
// pre-rounded (tf32-valued) copies of inputs
__device__ float g_hid_r[TT * HIDDEN];
__device__ float g_wq_r[HIDDEN * QW];
__device__ float g_wkva_r[HIDDEN * LATW];
__device__ float g_wkvb_r[KV_LORA * KVW];
__device__ float g_wo_r[NH * DVV * HIDDEN];

// ---------------- helpers -----------------------------------------------------
__device__ __forceinline__ uint32_t f2tf32(float x) {
    uint32_t r;
    asm("cvt.rna.tf32.f32 %0, %1;" : "=r"(r) : "f"(x));
    return r;
}
__device__ __forceinline__ float f2tf32f(float x) { return __uint_as_float(f2tf32(x)); }

__device__ __forceinline__ void mma_tf32(float c[4], const uint32_t a[4], const uint32_t b[2]) {
    asm volatile(
        "mma.sync.aligned.m16n8k8.row.col.f32.tf32.tf32.f32 "
        "{%0,%1,%2,%3}, {%4,%5,%6,%7}, {%8,%9}, {%0,%1,%2,%3};"
        : "+f"(c[0]), "+f"(c[1]), "+f"(c[2]), "+f"(c[3])
        : "r"(a[0]), "r"(a[1]), "r"(a[2]), "r"(a[3]), "r"(b[0]), "r"(b[1]));
}

__device__ __forceinline__ uint32_t smem_u32(const void* p) {
    return (uint32_t)__cvta_generic_to_shared(p);
}
__device__ __forceinline__ void cp16(uint32_t dst, const void* src, int src_bytes) {
    asm volatile("cp.async.cg.shared.global [%0], [%1], 16, %2;"
                 :: "r"(dst), "l"(src), "r"(src_bytes));
}
#define CP_COMMIT() asm volatile("cp.async.commit_group;")
#define CP_WAIT(n)  asm volatile("cp.async.wait_group %0;" :: "n"(n))

__device__ __forceinline__ void rope_pair(float p, int i, float& x1, float& x2) {
    float inv = 1.0f / powf(10000.0f, (float)(2 * i) / (float)DR);
    float f = p * inv;
    float c = cosf(f), s = sinf(f);
    float o1 = x1 * c - x2 * s;
    float o2 = x2 * c + x1 * s;
    x1 = o1; x2 = o2;
}

// ---------------- pre-round inputs to tf32 values -------------------------------
__global__ __launch_bounds__(256) void round_copy(
    const float* __restrict__ in, float* __restrict__ out, int n4)
{
    int i = blockIdx.x * 256 + threadIdx.x;
    if (i < n4) {
        float4 v = reinterpret_cast<const float4*>(in)[i];
        float4 o;
        o.x = f2tf32f(v.x); o.y = f2tf32f(v.y);
        o.z = f2tf32f(v.z); o.w = f2tf32f(v.w);
        reinterpret_cast<float4*>(out)[i] = o;
    }
}

// ---------------- TF32 GEMM: inputs pre-rounded, no cvt in inner loop -----------
#define GSTAGES 4
#define GA_STRIDE 36
#define GB_STRIDE 264
#define GAW (128 * GA_STRIDE)
#define GBW (32 * GB_STRIDE)
#define GSTAGE_W (GAW + GBW)
#define GEMM_SMEM (GSTAGES * GSTAGE_W * 4)  // 208896 B

__global__ __launch_bounds__(256, 1) void gemm_tf32_dual(
    const float* __restrict__ A,
    const float* __restrict__ B1, float* __restrict__ C1, int N1,
    const float* __restrict__ B2, float* __restrict__ C2, int N2,
    int K, int roundC)
{
    extern __shared__ float gsm[];
    const uint32_t smBase = smem_u32(gsm);

    const int tiles1 = (N1 + 255) / 256;
    const float* B; float* C; int N, n0;
    if ((int)blockIdx.x < tiles1) {
        B = B1; C = C1; N = N1; n0 = blockIdx.x * 256;
    } else {
        B = B2; C = C2; N = N2; n0 = (blockIdx.x - tiles1) * 256;
    }

    const int tid  = threadIdx.x;
    const int lane = tid & 31, warp = tid >> 5;
    const int warpM = warp & 1;
    const int warpN = warp >> 1;
    const int gid = lane >> 2, tig = lane & 3;
    const int m0 = blockIdx.y * 128;

    const int ar = tid >> 3, ac = (tid & 7) * 4;
    const int br = tid >> 6, bc = (tid & 63) * 4;

    const int nslab = K >> 5;

    auto issue_slab = [&](int slab) {
        const int k0 = slab * 32;
        const uint32_t stg = smBase + (uint32_t)((slab & (GSTAGES - 1)) * GSTAGE_W) * 4;
        #pragma unroll
        for (int i = 0; i < 4; i++) {
            uint32_t dst = stg + (uint32_t)((ar + 32 * i) * GA_STRIDE + ac) * 4;
            cp16(dst, &A[(size_t)(m0 + ar + 32 * i) * K + k0 + ac], 16);
        }
        const int col = n0 + bc;
        const int ok = (col < N) ? 16 : 0;
        #pragma unroll
        for (int i = 0; i < 8; i++) {
            uint32_t dst = stg + (uint32_t)(GAW + (br + 4 * i) * GB_STRIDE + bc) * 4;
            cp16(dst, &B[(size_t)(k0 + br + 4 * i) * N + col], ok);
        }
    };

    #pragma unroll
    for (int s = 0; s < GSTAGES - 1; s++) {
        if (s < nslab) issue_slab(s);
        CP_COMMIT();
    }

    float c[4][8][4] = {};

    for (int i = 0; i < nslab; i++) {
        CP_WAIT(GSTAGES - 2);
        __syncthreads();

        if (i + GSTAGES - 1 < nslab) issue_slab(i + GSTAGES - 1);
        CP_COMMIT();

        const uint32_t* Ab = (const uint32_t*)(gsm + (i & (GSTAGES - 1)) * GSTAGE_W);
        const uint32_t* Bb = Ab + GAW;

        #pragma unroll
        for (int ks = 0; ks < 4; ks++) {
            const int kb = ks * 8;
            uint32_t a[4][4], b[8][2];
            #pragma unroll
            for (int mt = 0; mt < 4; mt++) {
                int r = warpM * 64 + mt * 16 + gid;
                a[mt][0] = Ab[r * GA_STRIDE + kb + tig];
                a[mt][1] = Ab[(r + 8) * GA_STRIDE + kb + tig];
                a[mt][2] = Ab[r * GA_STRIDE + kb + tig + 4];
                a[mt][3] = Ab[(r + 8) * GA_STRIDE + kb + tig + 4];
            }
            #pragma unroll
            for (int nt = 0; nt < 8; nt++) {
                int cc = warpN * 64 + nt * 8 + gid;
                b[nt][0] = Bb[(kb + tig) * GB_STRIDE + cc];
                b[nt][1] = Bb[(kb + tig + 4) * GB_STRIDE + cc];
            }
            #pragma unroll
            for (int mt = 0; mt < 4; mt++)
                #pragma unroll
                for (int nt = 0; nt < 8; nt++)
                    mma_tf32(c[mt][nt], a[mt], b[nt]);
        }
    }

    #pragma unroll
    for (int mt = 0; mt < 4; mt++) {
        #pragma unroll
        for (int nt = 0; nt < 8; nt++) {
            int r = m0 + warpM * 64 + mt * 16 + gid;
            int cc = n0 + warpN * 64 + nt * 8 + tig * 2;
            if (cc < N) {
                float v0 = c[mt][nt][0], v1 = c[mt][nt][1];
                float v2 = c[mt][nt][2], v3 = c[mt][nt][3];
                if (roundC) {
                    v0 = f2tf32f(v0); v1 = f2tf32f(v1);
                    v2 = f2tf32f(v2); v3 = f2tf32f(v3);
                }
                *reinterpret_cast<float2*>(&C[(size_t)r * N + cc]) = make_float2(v0, v1);
                *reinterpret_cast<float2*>(&C[(size_t)(r + 8) * N + cc]) = make_float2(v2, v3);
            }
        }
    }
}

// ---------------- rmsnorm + rope_k fused (outputs tf32-rounded) -----------------
__global__ __launch_bounds__(256) void rmsnorm_ropek_kernel(
    const float* __restrict__ latent, const float* __restrict__ w,
    float* __restrict__ out, float* __restrict__ kpe)
{
    const int t = blockIdx.x;
    const float* x = latent + (size_t)t * LATW;
    __shared__ float red[8];
    float ss = 0.f;
    for (int i = threadIdx.x; i < KV_LORA; i += 256) { float v = x[i]; ss += v * v; }
    #pragma unroll
    for (int o = 16; o > 0; o >>= 1) ss += __shfl_xor_sync(~0u, ss, o);
    if ((threadIdx.x & 31) == 0) red[threadIdx.x >> 5] = ss;
    __syncthreads();
    if (threadIdx.x == 0) {
        float v = 0.f;
        #pragma unroll
        for (int i = 0; i < 8; i++) v += red[i];
        red[0] = v;
    }
    __syncthreads();
    const float inv = rsqrtf(red[0] / (float)KV_LORA + 1e-6f);
    for (int i = threadIdx.x; i < KV_LORA; i += 256)
        out[(size_t)t * KV_LORA + i] = f2tf32f(x[i] * inv * w[i]);

    if (threadIdx.x < DR / 2) {
        int i = threadIdx.x;
        float x1 = x[KV_LORA + 2 * i], x2 = x[KV_LORA + 2 * i + 1];
        rope_pair((float)t, i, x1, x2);
        kpe[(size_t)t * DR + 2 * i]     = f2tf32f(x1);
        kpe[(size_t)t * DR + 2 * i + 1] = f2tf32f(x2);
    }
}

// ---------------- tensor-core flash attention -----------------------------------
// K/V arrive pre-rounded: no convert passes. 3 barriers/tile. DVP=136 (no conflicts).
#define ABM 128
#define ABN 64
#define DQP (DQ + 4)    // 196
#define DVP (DVV + 8)   // 136
#define BNP (ABN + 4)   // 68
#define SQ_W (ABM * DQP)
#define SK_W (ABN * DQP)
#define SV_W (ABN * DVP)
#define SP_W (ABM * BNP)
#define ATTN_SMEM ((SQ_W + SK_W + SV_W + SP_W) * 4)  // 220160 B

__global__ __launch_bounds__(256) void mla_attn_tc(
    const float* __restrict__ q, const float* __restrict__ kv,
    const float* __restrict__ kpe, float* __restrict__ out)
{
    extern __shared__ uint32_t asm_[];
    uint32_t* sQ = asm_;
    uint32_t* sK = asm_ + SQ_W;
    uint32_t* sV = asm_ + SQ_W + SK_W;
    uint32_t* sP = asm_ + SQ_W + SK_W + SV_W;
    const uint32_t sKb = smem_u32(sK);
    const uint32_t sVb = smem_u32(sV);

    const int bx = (TT / ABM - 1) - ((int)blockIdx.x >> 4);  // LPT order
    const int h  = (int)blockIdx.x & (NH - 1);
    const int q0 = bx * ABM;
    const int tid = threadIdx.x;
    const int lane = tid & 31, warp = tid >> 5;
    const int gid = lane >> 2, tig = lane & 3;
    const int r0 = warp * 16;
    const float scale = rsqrtf((float)DQ);

    auto issueK = [&](int k0) {
        #pragma unroll
        for (int j = 0; j < 12; j++) {
            int c = j * 256 + tid;
            int r = c / 48, col4 = (c % 48) * 4;
            uint32_t dst = sKb + (uint32_t)(r * DQP + col4) * 4;
            const float* src = (col4 < DN)
                ? &kv[(size_t)(k0 + r) * KVW + h * (DN + DVV) + col4]
                : &kpe[(size_t)(k0 + r) * DR + (col4 - DN)];
            cp16(dst, src, 16);
        }
    };
    auto issueV = [&](int k0) {
        #pragma unroll
        for (int j = 0; j < 8; j++) {
            int c = j * 256 + tid;
            int r = c / 32, col4 = (c % 32) * 4;
            uint32_t dst = sVb + (uint32_t)(r * DVP + col4) * 4;
            cp16(dst, &kv[(size_t)(k0 + r) * KVW + h * (DN + DVV) + DN + col4], 16);
        }
    };

    issueK(0);
    CP_COMMIT();

    // Q nope part (scaled + rounded)
    for (int idx = tid; idx < ABM * DN; idx += 256) {
        int r = idx / DN, d = idx % DN;
        sQ[r * DQP + d] = f2tf32(q[(size_t)(q0 + r) * QW + h * DQ + d] * scale);
    }
    // Q pe part with fused rope
    for (int idx = tid; idx < ABM * (DR / 2); idx += 256) {
        int r = idx / (DR / 2), i = idx % (DR / 2);
        const float* bq = &q[(size_t)(q0 + r) * QW + h * DQ + DN];
        float x1 = bq[2 * i], x2 = bq[2 * i + 1];
        rope_pair((float)(q0 + r), i, x1, x2);
        sQ[r * DQP + DN + 2 * i]     = f2tf32(x1 * scale);
        sQ[r * DQP + DN + 2 * i + 1] = f2tf32(x2 * scale);
    }

    float o[16][4] = {};
    float m_a = -1e30f, m_b = -1e30f, l_a = 0.f, l_b = 0.f;
    const int jt_end = 2 * bx + 1;

    for (int jt = 0; jt <= jt_end; jt++) {
        const int k0 = jt * ABN;

        CP_WAIT(0);        // K(jt) landed
        __syncthreads();   // K + (jt==0: Q) visible; prev sV/sP reads done

        issueV(k0);
        CP_COMMIT();

        // ---- S = Q @ K^T (sK consumed raw: pre-rounded tf32) ----
        float s[8][4] = {};
        #pragma unroll 6
        for (int kb = 0; kb < DQ; kb += 8) {
            uint32_t a[4];
            a[0] = sQ[(r0 + gid) * DQP + kb + tig];
            a[1] = sQ[(r0 + gid + 8) * DQP + kb + tig];
            a[2] = sQ[(r0 + gid) * DQP + kb + tig + 4];
            a[3] = sQ[(r0 + gid + 8) * DQP + kb + tig + 4];
            #pragma unroll
            for (int nt = 0; nt < 8; nt++) {
                uint32_t b[2];
                b[0] = sK[(nt * 8 + gid) * DQP + kb + tig];
                b[1] = sK[(nt * 8 + gid) * DQP + kb + tig + 4];
                mma_tf32(s[nt], a, b);
            }
        }
        __syncthreads();   // sK free

        if (jt < jt_end) {
            issueK(k0 + ABN);
            CP_COMMIT();
        }

        if (jt >= 2 * bx) {
            const int rowA = q0 + r0 + gid;
            const int rowB = rowA + 8;
            #pragma unroll
            for (int nt = 0; nt < 8; nt++) {
                int c0 = k0 + nt * 8 + tig * 2;
                if (c0 > rowA)     s[nt][0] = -1e30f;
                if (c0 + 1 > rowA) s[nt][1] = -1e30f;
                if (c0 > rowB)     s[nt][2] = -1e30f;
                if (c0 + 1 > rowB) s[nt][3] = -1e30f;
            }
        }

        float mxa = -1e30f, mxb = -1e30f;
        #pragma unroll
        for (int nt = 0; nt < 8; nt++) {
            mxa = fmaxf(mxa, fmaxf(s[nt][0], s[nt][1]));
            mxb = fmaxf(mxb, fmaxf(s[nt][2], s[nt][3]));
        }
        mxa = fmaxf(mxa, __shfl_xor_sync(~0u, mxa, 1));
        mxa = fmaxf(mxa, __shfl_xor_sync(~0u, mxa, 2));
        mxb = fmaxf(mxb, __shfl_xor_sync(~0u, mxb, 1));
        mxb = fmaxf(mxb, __shfl_xor_sync(~0u, mxb, 2));

        float mna = fmaxf(m_a, mxa), mnb = fmaxf(m_b, mxb);
        float alpha_a = __expf(m_a - mna), alpha_b = __expf(m_b - mnb);
        float sa = 0.f, sb = 0.f;
        #pragma unroll
        for (int nt = 0; nt < 8; nt++) {
            s[nt][0] = __expf(s[nt][0] - mna);
            s[nt][1] = __expf(s[nt][1] - mna);
            s[nt][2] = __expf(s[nt][2] - mnb);
            s[nt][3] = __expf(s[nt][3] - mnb);
            sa += s[nt][0] + s[nt][1];
            sb += s[nt][2] + s[nt][3];
        }
        sa += __shfl_xor_sync(~0u, sa, 1); sa += __shfl_xor_sync(~0u, sa, 2);
        sb += __shfl_xor_sync(~0u, sb, 1); sb += __shfl_xor_sync(~0u, sb, 2);
        l_a = l_a * alpha_a + sa;
        l_b = l_b * alpha_b + sb;
        m_a = mna; m_b = mnb;

        #pragma unroll
        for (int nt = 0; nt < 16; nt++) {
            o[nt][0] *= alpha_a; o[nt][1] *= alpha_a;
            o[nt][2] *= alpha_b; o[nt][3] *= alpha_b;
        }

        // wait V(jt); K(jt+1) may stay in flight
        if (jt < jt_end) { CP_WAIT(1); } else { CP_WAIT(0); }
        __syncthreads();   // V visible

        // stash P (each warp owns its rows; PV reads only own rows)
        #pragma unroll
        for (int nt = 0; nt < 8; nt++) {
            sP[(r0 + gid) * BNP + nt * 8 + tig * 2]         = f2tf32(s[nt][0]);
            sP[(r0 + gid) * BNP + nt * 8 + tig * 2 + 1]     = f2tf32(s[nt][1]);
            sP[(r0 + gid + 8) * BNP + nt * 8 + tig * 2]     = f2tf32(s[nt][2]);
            sP[(r0 + gid + 8) * BNP + nt * 8 + tig * 2 + 1] = f2tf32(s[nt][3]);
        }
        __syncwarp();

        // ---- O += P @ V ----
        #pragma unroll
        for (int kb = 0; kb < ABN; kb += 8) {
            uint32_t a[4];
            a[0] = sP[(r0 + gid) * BNP + kb + tig];
            a[1] = sP[(r0 + gid + 8) * BNP + kb + tig];
            a[2] = sP[(r0 + gid) * BNP + kb + tig + 4];
            a[3] = sP[(r0 + gid + 8) * BNP + kb + tig + 4];
            #pragma unroll
            for (int nt = 0; nt < 16; nt++) {
                uint32_t b[2];
                b[0] = sV[(kb + tig) * DVP + nt * 8 + gid];
                b[1] = sV[(kb + tig + 4) * DVP + nt * 8 + gid];
                mma_tf32(o[nt], a, b);
            }
        }
    }

    // epilogue: round to tf32 here (g_attn is A-operand of the out GEMM)
    const float inv_a = 1.0f / l_a, inv_b = 1.0f / l_b;
    const int rowA = q0 + r0 + gid, rowB = rowA + 8;
    #pragma unroll
    for (int nt = 0; nt < 16; nt++) {
        int cc = h * DVV + nt * 8 + tig * 2;
        *reinterpret_cast<float2*>(&out[(size_t)rowA * (NH * DVV) + cc]) =
            make_float2(f2tf32f(o[nt][0] * inv_a), f2tf32f(o[nt][1] * inv_a));
        *reinterpret_cast<float2*>(&out[(size_t)rowB * (NH * DVV) + cc]) =
            make_float2(f2tf32f(o[nt][2] * inv_b), f2tf32f(o[nt][3] * inv_b));
    }
}

// ---------------- launch --------------------------------------------------------
extern "C" void kernel_launch(void* const* d_in, const int* in_sizes, int n_in,
                              void* d_out, int out_size)
{
    const float* hidden = (const float*)d_in[1];
    const float* w_q    = (const float*)d_in[2];
    const float* w_kv_a = (const float*)d_in[3];
    const float* ln_w   = (const float*)d_in[4];
    const float* w_kv_b = (const float*)d_in[5];
    const float* w_o    = (const float*)d_in[6];
    float* out = (float*)d_out;

    float *q_p, *lat_p, *kva_p, *kpe_p, *kv_p, *attn_p;
    float *hid_r, *wq_r, *wkva_r, *wkvb_r, *wo_r;
    cudaGetSymbolAddress((void**)&q_p,    g_q);
    cudaGetSymbolAddress((void**)&lat_p,  g_latent);
    cudaGetSymbolAddress((void**)&kva_p,  g_kva);
    cudaGetSymbolAddress((void**)&kpe_p,  g_kpe);
    cudaGetSymbolAddress((void**)&kv_p,   g_kv);
    cudaGetSymbolAddress((void**)&attn_p, g_attn);
    cudaGetSymbolAddress((void**)&hid_r,  g_hid_r);
    cudaGetSymbolAddress((void**)&wq_r,   g_wq_r);
    cudaGetSymbolAddress((void**)&wkva_r, g_wkva_r);
    cudaGetSymbolAddress((void**)&wkvb_r, g_wkvb_r);
    cudaGetSymbolAddress((void**)&wo_r,   g_wo_r);

    cudaFuncSetAttribute(gemm_tf32_dual,
                         cudaFuncAttributeMaxDynamicSharedMemorySize, GEMM_SMEM);
    cudaFuncSetAttribute(mla_attn_tc,
                         cudaFuncAttributeMaxDynamicSharedMemorySize, ATTN_SMEM);

    dim3 blk(256);

    // pre-round inputs (tf32 values stored as float bits)
    {
        int n;
        n = TT * HIDDEN / 4;      round_copy<<<(n + 255) / 256, blk>>>(hidden, hid_r, n);
        n = HIDDEN * QW / 4;      round_copy<<<(n + 255) / 256, blk>>>(w_q, wq_r, n);
        n = HIDDEN * LATW / 4;    round_copy<<<(n + 255) / 256, blk>>>(w_kv_a, wkva_r, n);
        n = KV_LORA * KVW / 4;    round_copy<<<(n + 255) / 256, blk>>>(w_kv_b, wkvb_r, n);
        n = NH * DVV * HIDDEN / 4; round_copy<<<(n + 255) / 256, blk>>>(w_o, wo_r, n);
    }

    const int t1 = QW / 256;                 // 12
    const int t2 = (LATW + 255) / 256;       // 3

    // fused: q = hidden@w_q AND latent = hidden@w_kv_a (outputs stay fp32)
    gemm_tf32_dual<<<dim3(t1 + t2, TT / 128), blk, GEMM_SMEM>>>(
        hid_r, wq_r, q_p, QW, wkva_r, lat_p, LATW, HIDDEN, 0);
    // rmsnorm + rope_k fused (outputs tf32-rounded)
    rmsnorm_ropek_kernel<<<TT, 256>>>(lat_p, ln_w, kva_p, kpe_p);
    // kv = kva @ w_kv_b (output tf32-rounded: feeds attention K/V raw)
    gemm_tf32_dual<<<dim3(KVW / 256, TT / 128), blk, GEMM_SMEM>>>(
        kva_p, wkvb_r, kv_p, KVW, (const float*)nullptr, (float*)nullptr, 0, KV_LORA, 1);
    // attention (LPT; rope_q fused; epilogue rounds g_attn)
    mla_attn_tc<<<(TT / ABM) * NH, blk, ATTN_SMEM>>>(q_p, kv_p, kpe_p, attn_p);
    // out = attn @ w_o (output fp32)
    gemm_tf32_dual<<<dim3(HIDDEN / 256, TT / 128), blk, GEMM_SMEM>>>(
        attn_p, wo_r, out, HIDDEN, (const float*)nullptr, (float*)nullptr, 0, NH * DVV, 0);
}